// round 4
// baseline (speedup 1.0000x reference)
#include <cuda_runtime.h>
#include <cstdint>

#define N_NODES 100000
#define N_EDGES 1600000
#define D 128
#define L 3

#define AS 36                       // padded row stride (words) per 32-k chunk
#define CHUNK_W (128 * AS)          // words per chunk tile = 4608
#define SMEM_WORDS (5 * CHUNK_W + 128)
#define SMEM_BYTES (SMEM_WORDS * 4) // 92672 bytes

// ---------------- scratch (device globals; no allocation allowed) ----------
__device__ __align__(16) float g_buf0[N_NODES * D];
__device__ __align__(16) float g_buf1[N_NODES * D];
__device__ float    g_inv [N_NODES];       // 1 / max(count,1)
__device__ int      g_cnt [N_NODES];
__device__ int      g_off [N_NODES + 1];   // CSR offsets (by dst)
__device__ int      g_cur [N_NODES];       // fill cursors
__device__ int      g_adj [N_EDGES];       // CSR adjacency: src lists per dst
__device__ unsigned g_minbuf[D];           // monotone-uint min accumulator

// monotone mapping: order-preserving float -> uint
__device__ __forceinline__ unsigned f2mono(float f) {
    unsigned u = __float_as_uint(f);
    return (u & 0x80000000u) ? ~u : (u | 0x80000000u);
}
__device__ __forceinline__ float mono2f(unsigned m) {
    return (m & 0x80000000u) ? __uint_as_float(m ^ 0x80000000u)
                             : __uint_as_float(~m);
}
__device__ __forceinline__ uint32_t f2tf32(float f) {
    uint32_t u;
    asm("cvt.rna.tf32.f32 %0, %1;" : "=r"(u) : "f"(f));
    return u;
}

// ---------------- init ------------------------------------------------------
__global__ void k_init(void) {
    int i = blockIdx.x * blockDim.x + threadIdx.x;
    if (i < N_NODES) g_cnt[i] = 0;
    if (i < D)       g_minbuf[i] = 0xFFFFFFFFu;
}

// ---------------- degree histogram -----------------------------------------
__global__ void k_count(const int* __restrict__ ei) {
    int e = blockIdx.x * blockDim.x + threadIdx.x;
    if (e >= N_EDGES) return;
    atomicAdd(&g_cnt[ei[N_EDGES + e]], 1);
}

// ---------------- single-block scan -> offsets + cursors + inv --------------
__global__ void __launch_bounds__(1024) k_scan(void) {
    __shared__ int ssum[1024];
    const int CH = (N_NODES + 1023) / 1024;   // 98
    int tid  = threadIdx.x;
    int base = tid * CH;
    int s = 0;
    for (int i = 0; i < CH; i++) {
        int idx = base + i;
        if (idx < N_NODES) s += g_cnt[idx];
    }
    ssum[tid] = s;
    __syncthreads();
    for (int off = 1; off < 1024; off <<= 1) {
        int v = (tid >= off) ? ssum[tid - off] : 0;
        __syncthreads();
        ssum[tid] += v;
        __syncthreads();
    }
    int run = (tid > 0) ? ssum[tid - 1] : 0;
    for (int i = 0; i < CH; i++) {
        int idx = base + i;
        if (idx < N_NODES) {
            int cnt = g_cnt[idx];
            g_off[idx] = run;
            g_cur[idx] = run;
            g_inv[idx] = 1.0f / fmaxf((float)cnt, 1.0f);
            run += cnt;
        }
    }
    if (tid == 1023) g_off[N_NODES] = ssum[1023];
}

// ---------------- CSR fill ---------------------------------------------------
__global__ void k_fill(const int* __restrict__ ei) {
    int e = blockIdx.x * blockDim.x + threadIdx.x;
    if (e >= N_EDGES) return;
    int src = ei[e];
    int dst = ei[N_EDGES + e];
    int pos = atomicAdd(&g_cur[dst], 1);
    g_adj[pos] = src;
}

// ---------------- tf32 MMA helper -------------------------------------------
__device__ __forceinline__ void mma_tf32(float* d, const uint32_t* a,
                                         uint32_t b0, uint32_t b1) {
    asm volatile(
        "mma.sync.aligned.m16n8k8.row.col.f32.tf32.tf32.f32 "
        "{%0,%1,%2,%3}, {%4,%5,%6,%7}, {%8,%9}, {%0,%1,%2,%3};"
        : "+f"(d[0]), "+f"(d[1]), "+f"(d[2]), "+f"(d[3])
        : "r"(a[0]), "r"(a[1]), "r"(a[2]), "r"(a[3]), "r"(b0), "r"(b1));
}

// ---------------- fused SAGE layer: gather + GEMM (+ optional min) ----------
// Phase 1: 8 warps gather means of 128 nodes directly into smem As_mean
//          (tf32, k-permuted layout: chunk = k/32, within chunk pos =
//           2*(k&3)+((k>>2)&1) inside k8-group).
// Phase 2: 8 chunks of K=256 ([mean | x] vs [Wl | Wr]); x chunks reuse the
//          already-consumed mean chunk buffers as staging.
// MINF: skip the 51MB store; fold column-min into the epilogue.
template<int RELU, int MINF>
__global__ void __launch_bounds__(256)
k_fused(const float* __restrict__ xcur,
        const float* __restrict__ Wl,
        const float* __restrict__ bl,
        const float* __restrict__ Wr,
        float* __restrict__ xnext) {
    extern __shared__ uint32_t smem[];
    uint32_t* Bs   = smem + 4 * CHUNK_W;
    unsigned* sMin = (unsigned*)(smem + 5 * CHUNK_W);

    int tid    = threadIdx.x;
    int wid    = tid >> 5;
    int lane   = tid & 31;
    int g      = lane >> 2;
    int c      = lane & 3;
    int warp_m = wid & 3;
    int warp_n = wid >> 2;
    int blockRow = blockIdx.x * 128;

    if (MINF && tid < 128) sMin[tid] = 0xFFFFFFFFu;

    // ---- Phase 1: gather means into As_mean ----
    {
        int chunkIdx = lane >> 3;            // which 32-k chunk my 4 cols land in
        int kg       = (lane & 7) >> 1;      // k8-group within chunk
        int odd      = lane & 1;             // permuted offset parity
        for (int i = 0; i < 16; i++) {
            int r = wid * 16 + i;
            int node = blockRow + r;
            float4 acc = make_float4(0.f, 0.f, 0.f, 0.f);
            if (node < N_NODES) {
                int off0 = g_off[node];
                int off1 = g_off[node + 1];
                int p = off0;
                for (; p + 4 <= off1; p += 4) {
                    int nb0 = g_adj[p + 0];
                    int nb1 = g_adj[p + 1];
                    int nb2 = g_adj[p + 2];
                    int nb3 = g_adj[p + 3];
                    float4 v0 = ((const float4*)(xcur + (long long)nb0 * D))[lane];
                    float4 v1 = ((const float4*)(xcur + (long long)nb1 * D))[lane];
                    float4 v2 = ((const float4*)(xcur + (long long)nb2 * D))[lane];
                    float4 v3 = ((const float4*)(xcur + (long long)nb3 * D))[lane];
                    acc.x += v0.x + v1.x + v2.x + v3.x;
                    acc.y += v0.y + v1.y + v2.y + v3.y;
                    acc.z += v0.z + v1.z + v2.z + v3.z;
                    acc.w += v0.w + v1.w + v2.w + v3.w;
                }
                for (; p < off1; p++) {
                    int nb = g_adj[p];
                    float4 v = ((const float4*)(xcur + (long long)nb * D))[lane];
                    acc.x += v.x; acc.y += v.y; acc.z += v.z; acc.w += v.w;
                }
                float s = g_inv[node];
                acc.x *= s; acc.y *= s; acc.z *= s; acc.w *= s;
            }
            uint32_t* dst = smem + chunkIdx * CHUNK_W + r * AS + kg * 8 + odd;
            dst[0] = f2tf32(acc.x);
            dst[2] = f2tf32(acc.y);
            dst[4] = f2tf32(acc.z);
            dst[6] = f2tf32(acc.w);
        }
    }
    __syncthreads();

    // ---- Phase 2: MMA over 8 chunks of K=256 ----
    float acc[2][8][4];
#pragma unroll
    for (int mt = 0; mt < 2; mt++)
#pragma unroll
        for (int nt = 0; nt < 8; nt++)
#pragma unroll
            for (int r = 0; r < 4; r++) acc[mt][nt][r] = 0.f;

    for (int kc = 0; kc < 8; kc++) {
        bool meanRegion = (kc < 4);
        int  kb = meanRegion ? kc * 32 : (kc - 4) * 32;
        uint32_t* Achunk = smem + (meanRegion ? kc : kc - 4) * CHUNK_W;

        if (!meanRegion) {
            // stage x chunk into the consumed mean buffer
#pragma unroll
            for (int t = 0; t < 4; t++) {
                int idx = tid + t * 256;
                int r   = idx >> 3;
                int k4  = (idx & 7) * 4;
                int n   = blockRow + r;
                if (n >= N_NODES) n = N_NODES - 1;
                float4 v = *(const float4*)(xcur + (long long)n * D + kb + k4);
                int kg  = k4 >> 3;
                int odd = (k4 & 4) ? 1 : 0;
                uint32_t* dst = &Achunk[r * AS + kg * 8 + odd];
                dst[0] = f2tf32(v.x);
                dst[2] = f2tf32(v.y);
                dst[4] = f2tf32(v.z);
                dst[6] = f2tf32(v.w);
            }
        }
        // stage B chunk
        const float* Wsrc = meanRegion ? Wl : Wr;
#pragma unroll
        for (int t = 0; t < 4; t++) {
            int idx = tid + t * 256;
            int j   = idx >> 3;
            int k4  = (idx & 7) * 4;
            float4 v = *(const float4*)(Wsrc + j * D + kb + k4);
            int kg  = k4 >> 3;
            int odd = (k4 & 4) ? 1 : 0;
            uint32_t* dst = &Bs[j * AS + kg * 8 + odd];
            dst[0] = f2tf32(v.x);
            dst[2] = f2tf32(v.y);
            dst[4] = f2tf32(v.z);
            dst[6] = f2tf32(v.w);
        }
        __syncthreads();

#pragma unroll
        for (int ks = 0; ks < 4; ks++) {
            uint32_t a[2][4];
#pragma unroll
            for (int mt = 0; mt < 2; mt++) {
                int row = warp_m * 32 + mt * 16 + g;
                uint2 lo = *(uint2*)&Achunk[row * AS + ks * 8 + 2 * c];
                uint2 hi = *(uint2*)&Achunk[(row + 8) * AS + ks * 8 + 2 * c];
                a[mt][0] = lo.x; a[mt][2] = lo.y;
                a[mt][1] = hi.x; a[mt][3] = hi.y;
            }
#pragma unroll
            for (int nt = 0; nt < 8; nt++) {
                int col = warp_n * 64 + nt * 8 + g;
                uint2 b = *(uint2*)&Bs[col * AS + ks * 8 + 2 * c];
                mma_tf32(acc[0][nt], a[0], b.x, b.y);
                mma_tf32(acc[1][nt], a[1], b.x, b.y);
            }
        }
        __syncthreads();
    }

    // ---- epilogue ----
#pragma unroll
    for (int nt = 0; nt < 8; nt++) {
        int col = warp_n * 64 + nt * 8 + 2 * c;
        float b0 = bl[col];
        float b1 = bl[col + 1];
        if (MINF) {
            float m0 = 3.4e38f, m1 = 3.4e38f;
#pragma unroll
            for (int mt = 0; mt < 2; mt++) {
                int row0 = blockRow + warp_m * 32 + mt * 16 + g;
                if (row0 < N_NODES) {
                    m0 = fminf(m0, acc[mt][nt][0] + b0);
                    m1 = fminf(m1, acc[mt][nt][1] + b1);
                }
                if (row0 + 8 < N_NODES) {
                    m0 = fminf(m0, acc[mt][nt][2] + b0);
                    m1 = fminf(m1, acc[mt][nt][3] + b1);
                }
            }
            // reduce over the 8 g row-groups within the warp
#pragma unroll
            for (int s = 16; s >= 4; s >>= 1) {
                m0 = fminf(m0, __shfl_xor_sync(0xFFFFFFFFu, m0, s));
                m1 = fminf(m1, __shfl_xor_sync(0xFFFFFFFFu, m1, s));
            }
            if (g == 0) {
                atomicMin(&sMin[col],     f2mono(m0));
                atomicMin(&sMin[col + 1], f2mono(m1));
            }
        } else {
#pragma unroll
            for (int mt = 0; mt < 2; mt++) {
                int row0 = blockRow + warp_m * 32 + mt * 16 + g;
                float v0 = acc[mt][nt][0] + b0;
                float v1 = acc[mt][nt][1] + b1;
                float v2 = acc[mt][nt][2] + b0;
                float v3 = acc[mt][nt][3] + b1;
                if (RELU) {
                    v0 = fmaxf(v0, 0.f); v1 = fmaxf(v1, 0.f);
                    v2 = fmaxf(v2, 0.f); v3 = fmaxf(v3, 0.f);
                }
                if (row0 < N_NODES)
                    *(float2*)(xnext + (long long)row0 * D + col) = make_float2(v0, v1);
                if (row0 + 8 < N_NODES)
                    *(float2*)(xnext + (long long)(row0 + 8) * D + col) = make_float2(v2, v3);
            }
        }
    }

    if (MINF) {
        __syncthreads();
        if (tid < 128) atomicMin(&g_minbuf[tid], sMin[tid]);
    }
}

// ---------------- final writeout --------------------------------------------
__global__ void k_writeout(float* __restrict__ out) {
    int j = threadIdx.x;
    out[j] = mono2f(g_minbuf[j]);
}

// ---------------- launch ----------------------------------------------------
extern "C" void kernel_launch(void* const* d_in, const int* in_sizes, int n_in,
                              void* d_out, int out_size) {
    const float* x  = (const float*)d_in[0];
    const int*   ei = (const int*)d_in[1];       // int32 edge index
    const float* Wl = (const float*)d_in[2];     // [L,D,D]
    const float* bl = (const float*)d_in[3];     // [L,D]
    const float* Wr = (const float*)d_in[4];     // [L,D,D]
    float*       out = (float*)d_out;

    // allow >48KB dynamic smem (idempotent; host-side, capture-safe)
    cudaFuncSetAttribute(k_fused<1,0>, cudaFuncAttributeMaxDynamicSharedMemorySize, SMEM_BYTES);
    cudaFuncSetAttribute(k_fused<0,1>, cudaFuncAttributeMaxDynamicSharedMemorySize, SMEM_BYTES);

    // ---- CSR build (once per launch)
    k_init <<<(N_NODES + 255) / 256, 256>>>();
    k_count<<<(N_EDGES + 255) / 256, 256>>>(ei);
    k_scan <<<1, 1024>>>();
    k_fill <<<(N_EDGES + 255) / 256, 256>>>(ei);

    float* bufs[2];
    cudaGetSymbolAddress((void**)&bufs[0], g_buf0);
    cudaGetSymbolAddress((void**)&bufs[1], g_buf1);

    const int blocks = (N_NODES + 127) / 128;    // 782

    const float* cur = x;
    for (int layer = 0; layer < L; layer++) {
        float* nxt = bufs[layer & 1];
        const float* wl = Wl + (long long)layer * D * D;
        const float* wr = Wr + (long long)layer * D * D;
        const float* b  = bl + (long long)layer * D;
        if (layer < L - 1)
            k_fused<1,0><<<blocks, 256, SMEM_BYTES>>>(cur, wl, b, wr, nxt);
        else
            k_fused<0,1><<<blocks, 256, SMEM_BYTES>>>(cur, wl, b, wr, nxt);
        cur = nxt;
    }

    k_writeout<<<1, D>>>(out);
}

// round 5
// speedup vs baseline: 1.2776x; 1.2776x over previous
#include <cuda_runtime.h>
#include <cstdint>

#define N_NODES 100000
#define N_EDGES 1600000
#define D 128
#define L 3

// ---------------- scratch (device globals; no allocation allowed) ----------
__device__ __align__(16) float g_agg [N_NODES * D];   // mean-aggregated features
__device__ __align__(16) float g_buf0[N_NODES * D];   // ping-pong feature buffers
__device__ __align__(16) float g_buf1[N_NODES * D];
__device__ float    g_inv [N_NODES];       // 1 / max(count,1)
__device__ int      g_cnt [N_NODES];
__device__ int      g_off [N_NODES + 1];   // CSR offsets (by dst)
__device__ int      g_cur [N_NODES];       // fill cursors
__device__ int      g_adj [N_EDGES];       // CSR adjacency: src lists per dst
__device__ unsigned g_minbuf[D];           // monotone-uint min accumulator

// monotone mapping: order-preserving float -> uint
__device__ __forceinline__ unsigned f2mono(float f) {
    unsigned u = __float_as_uint(f);
    return (u & 0x80000000u) ? ~u : (u | 0x80000000u);
}
__device__ __forceinline__ float mono2f(unsigned m) {
    return (m & 0x80000000u) ? __uint_as_float(m ^ 0x80000000u)
                             : __uint_as_float(~m);
}
__device__ __forceinline__ uint32_t f2tf32(float f) {
    uint32_t u;
    asm("cvt.rna.tf32.f32 %0, %1;" : "=r"(u) : "f"(f));
    return u;
}

// ---------------- init ------------------------------------------------------
__global__ void k_init(void) {
    int i = blockIdx.x * blockDim.x + threadIdx.x;
    if (i < N_NODES) g_cnt[i] = 0;
    if (i < D)       g_minbuf[i] = 0xFFFFFFFFu;
}

// ---------------- degree histogram -----------------------------------------
__global__ void k_count(const int* __restrict__ ei) {
    int e = blockIdx.x * blockDim.x + threadIdx.x;
    if (e >= N_EDGES) return;
    atomicAdd(&g_cnt[ei[N_EDGES + e]], 1);
}

// ---------------- single-block scan -> offsets + cursors + inv --------------
__global__ void __launch_bounds__(1024) k_scan(void) {
    __shared__ int ssum[1024];
    const int CH = (N_NODES + 1023) / 1024;   // 98
    int tid  = threadIdx.x;
    int base = tid * CH;
    int s = 0;
    for (int i = 0; i < CH; i++) {
        int idx = base + i;
        if (idx < N_NODES) s += g_cnt[idx];
    }
    ssum[tid] = s;
    __syncthreads();
    for (int off = 1; off < 1024; off <<= 1) {
        int v = (tid >= off) ? ssum[tid - off] : 0;
        __syncthreads();
        ssum[tid] += v;
        __syncthreads();
    }
    int run = (tid > 0) ? ssum[tid - 1] : 0;
    for (int i = 0; i < CH; i++) {
        int idx = base + i;
        if (idx < N_NODES) {
            int cnt = g_cnt[idx];
            g_off[idx] = run;
            g_cur[idx] = run;
            g_inv[idx] = 1.0f / fmaxf((float)cnt, 1.0f);
            run += cnt;
        }
    }
    if (tid == 1023) g_off[N_NODES] = ssum[1023];
}

// ---------------- CSR fill ---------------------------------------------------
__global__ void k_fill(const int* __restrict__ ei) {
    int e = blockIdx.x * blockDim.x + threadIdx.x;
    if (e >= N_EDGES) return;
    int src = ei[e];
    int dst = ei[N_EDGES + e];
    int pos = atomicAdd(&g_cur[dst], 1);
    g_adj[pos] = src;
}

// ---------------- per-layer mean gather: one warp per node ------------------
__global__ void __launch_bounds__(256) k_gather(const float* __restrict__ xcur) {
    int wid  = (blockIdx.x * blockDim.x + threadIdx.x) >> 5;
    int lane = threadIdx.x & 31;
    if (wid >= N_NODES) return;
    int node = wid;

    int off0 = g_off[node];
    int off1 = g_off[node + 1];

    float4 acc = make_float4(0.f, 0.f, 0.f, 0.f);
    int i = off0;
    for (; i + 4 <= off1; i += 4) {
        int nb0 = g_adj[i + 0];
        int nb1 = g_adj[i + 1];
        int nb2 = g_adj[i + 2];
        int nb3 = g_adj[i + 3];
        float4 v0 = ((const float4*)(xcur + (long long)nb0 * D))[lane];
        float4 v1 = ((const float4*)(xcur + (long long)nb1 * D))[lane];
        float4 v2 = ((const float4*)(xcur + (long long)nb2 * D))[lane];
        float4 v3 = ((const float4*)(xcur + (long long)nb3 * D))[lane];
        acc.x += v0.x + v1.x + v2.x + v3.x;
        acc.y += v0.y + v1.y + v2.y + v3.y;
        acc.z += v0.z + v1.z + v2.z + v3.z;
        acc.w += v0.w + v1.w + v2.w + v3.w;
    }
    for (; i < off1; i++) {
        int nb = g_adj[i];
        float4 v = ((const float4*)(xcur + (long long)nb * D))[lane];
        acc.x += v.x; acc.y += v.y; acc.z += v.z; acc.w += v.w;
    }
    float s = g_inv[node];
    acc.x *= s; acc.y *= s; acc.z *= s; acc.w *= s;
    ((float4*)(g_agg + (long long)node * D))[lane] = acc;
}

// ---------------- tf32 tensor-core fused SAGE GEMM --------------------------
// Block: 128 nodes x 128 cols, BK=32, 256 threads = 8 warps (4m x 2n),
// warp tile 32x64: 2 m16-tiles x 8 n8-tiles of mma.m16n8k8.tf32.
// MINF=1: fold column-wise min into epilogue, skip xnext store.
#define AS 36

__device__ __forceinline__ void mma_tf32(float* d, const uint32_t* a,
                                         uint32_t b0, uint32_t b1) {
    asm volatile(
        "mma.sync.aligned.m16n8k8.row.col.f32.tf32.tf32.f32 "
        "{%0,%1,%2,%3}, {%4,%5,%6,%7}, {%8,%9}, {%0,%1,%2,%3};"
        : "+f"(d[0]), "+f"(d[1]), "+f"(d[2]), "+f"(d[3])
        : "r"(a[0]), "r"(a[1]), "r"(a[2]), "r"(a[3]), "r"(b0), "r"(b1));
}

template<int RELU, int MINF>
__global__ void __launch_bounds__(256)
k_gemm(const float* __restrict__ xcur,
       const float* __restrict__ Wl,
       const float* __restrict__ bl,
       const float* __restrict__ Wr,
       float* __restrict__ xnext) {
    __shared__ uint32_t As[128 * AS];
    __shared__ uint32_t Bs[128 * AS];
    __shared__ unsigned sMin[128];

    int tid    = threadIdx.x;
    int wid    = tid >> 5;
    int lane   = tid & 31;
    int g      = lane >> 2;
    int c      = lane & 3;
    int warp_m = wid & 3;
    int warp_n = wid >> 2;
    int blockRow = blockIdx.x * 128;

    if (MINF && tid < 128) sMin[tid] = 0xFFFFFFFFu;

    float acc[2][8][4];
#pragma unroll
    for (int mt = 0; mt < 2; mt++)
#pragma unroll
        for (int nt = 0; nt < 8; nt++)
#pragma unroll
            for (int r = 0; r < 4; r++) acc[mt][nt][r] = 0.f;

    for (int kc = 0; kc < 8; kc++) {
        bool meanRegion = (kc < 4);
        int  kb = meanRegion ? kc * 32 : (kc - 4) * 32;
        const float* Asrc = meanRegion ? g_agg : xcur;
        const float* Wsrc = meanRegion ? Wl : Wr;

#pragma unroll
        for (int t = 0; t < 4; t++) {
            int idx = tid + t * 256;
            int r   = idx >> 3;
            int k4  = (idx & 7) * 4;
            int n   = blockRow + r;
            if (n >= N_NODES) n = N_NODES - 1;
            float4 v = *(const float4*)(Asrc + (long long)n * D + kb + k4);
            int kg  = k4 >> 3;
            int odd = (k4 & 4) ? 1 : 0;
            uint32_t* dst = &As[r * AS + kg * 8 + odd];
            dst[0] = f2tf32(v.x);
            dst[2] = f2tf32(v.y);
            dst[4] = f2tf32(v.z);
            dst[6] = f2tf32(v.w);
        }
#pragma unroll
        for (int t = 0; t < 4; t++) {
            int idx = tid + t * 256;
            int j   = idx >> 3;
            int k4  = (idx & 7) * 4;
            float4 v = *(const float4*)(Wsrc + j * D + kb + k4);
            int kg  = k4 >> 3;
            int odd = (k4 & 4) ? 1 : 0;
            uint32_t* dst = &Bs[j * AS + kg * 8 + odd];
            dst[0] = f2tf32(v.x);
            dst[2] = f2tf32(v.y);
            dst[4] = f2tf32(v.z);
            dst[6] = f2tf32(v.w);
        }
        __syncthreads();

#pragma unroll
        for (int ks = 0; ks < 4; ks++) {
            uint32_t a[2][4];
#pragma unroll
            for (int mt = 0; mt < 2; mt++) {
                int row = warp_m * 32 + mt * 16 + g;
                uint2 lo = *(uint2*)&As[row * AS + ks * 8 + 2 * c];
                uint2 hi = *(uint2*)&As[(row + 8) * AS + ks * 8 + 2 * c];
                a[mt][0] = lo.x; a[mt][2] = lo.y;
                a[mt][1] = hi.x; a[mt][3] = hi.y;
            }
#pragma unroll
            for (int nt = 0; nt < 8; nt++) {
                int col = warp_n * 64 + nt * 8 + g;
                uint2 b = *(uint2*)&Bs[col * AS + ks * 8 + 2 * c];
                mma_tf32(acc[0][nt], a[0], b.x, b.y);
                mma_tf32(acc[1][nt], a[1], b.x, b.y);
            }
        }
        __syncthreads();
    }

    // ---- epilogue ----
#pragma unroll
    for (int nt = 0; nt < 8; nt++) {
        int col = warp_n * 64 + nt * 8 + 2 * c;
        float b0 = bl[col];
        float b1 = bl[col + 1];
        if (MINF) {
            float m0 = 3.4e38f, m1 = 3.4e38f;
#pragma unroll
            for (int mt = 0; mt < 2; mt++) {
                int row0 = blockRow + warp_m * 32 + mt * 16 + g;
                if (row0 < N_NODES) {
                    m0 = fminf(m0, acc[mt][nt][0] + b0);
                    m1 = fminf(m1, acc[mt][nt][1] + b1);
                }
                if (row0 + 8 < N_NODES) {
                    m0 = fminf(m0, acc[mt][nt][2] + b0);
                    m1 = fminf(m1, acc[mt][nt][3] + b1);
                }
            }
#pragma unroll
            for (int s = 16; s >= 4; s >>= 1) {
                m0 = fminf(m0, __shfl_xor_sync(0xFFFFFFFFu, m0, s));
                m1 = fminf(m1, __shfl_xor_sync(0xFFFFFFFFu, m1, s));
            }
            if (g == 0) {
                atomicMin(&sMin[col],     f2mono(m0));
                atomicMin(&sMin[col + 1], f2mono(m1));
            }
        } else {
#pragma unroll
            for (int mt = 0; mt < 2; mt++) {
                int row0 = blockRow + warp_m * 32 + mt * 16 + g;
                float v0 = acc[mt][nt][0] + b0;
                float v1 = acc[mt][nt][1] + b1;
                float v2 = acc[mt][nt][2] + b0;
                float v3 = acc[mt][nt][3] + b1;
                if (RELU) {
                    v0 = fmaxf(v0, 0.f); v1 = fmaxf(v1, 0.f);
                    v2 = fmaxf(v2, 0.f); v3 = fmaxf(v3, 0.f);
                }
                if (row0 < N_NODES)
                    *(float2*)(xnext + (long long)row0 * D + col) = make_float2(v0, v1);
                if (row0 + 8 < N_NODES)
                    *(float2*)(xnext + (long long)(row0 + 8) * D + col) = make_float2(v2, v3);
            }
        }
    }

    if (MINF) {
        __syncthreads();
        if (tid < 128) atomicMin(&g_minbuf[tid], sMin[tid]);
    }
}

// ---------------- final writeout --------------------------------------------
__global__ void k_writeout(float* __restrict__ out) {
    int j = threadIdx.x;
    out[j] = mono2f(g_minbuf[j]);
}

// ---------------- launch ----------------------------------------------------
extern "C" void kernel_launch(void* const* d_in, const int* in_sizes, int n_in,
                              void* d_out, int out_size) {
    const float* x  = (const float*)d_in[0];
    const int*   ei = (const int*)d_in[1];       // int32 edge index
    const float* Wl = (const float*)d_in[2];     // [L,D,D]
    const float* bl = (const float*)d_in[3];     // [L,D]
    const float* Wr = (const float*)d_in[4];     // [L,D,D]
    float*       out = (float*)d_out;

    // ---- CSR build (once per launch)
    k_init <<<(N_NODES + 255) / 256, 256>>>();
    k_count<<<(N_EDGES + 255) / 256, 256>>>(ei);
    k_scan <<<1, 1024>>>();
    k_fill <<<(N_EDGES + 255) / 256, 256>>>(ei);

    float* bufs[2];
    cudaGetSymbolAddress((void**)&bufs[0], g_buf0);
    cudaGetSymbolAddress((void**)&bufs[1], g_buf1);

    const int gemmBlocks   = (N_NODES + 127) / 128;        // 782
    const int gatherBlocks = (N_NODES + 7) / 8;            // 12500 (8 warps/block)

    const float* cur = x;
    for (int layer = 0; layer < L; layer++) {
        float* nxt = bufs[layer & 1];
        k_gather<<<gatherBlocks, 256>>>(cur);
        const float* wl = Wl + (long long)layer * D * D;
        const float* wr = Wr + (long long)layer * D * D;
        const float* b  = bl + (long long)layer * D;
        if (layer < L - 1)
            k_gemm<1,0><<<gemmBlocks, 256>>>(cur, wl, b, wr, nxt);
        else
            k_gemm<0,1><<<gemmBlocks, 256>>>(cur, wl, b, wr, nxt);
        cur = nxt;
    }

    k_writeout<<<1, D>>>(out);
}

// round 6
// speedup vs baseline: 1.3954x; 1.0922x over previous
#include <cuda_runtime.h>
#include <cstdint>

#define N_NODES 100000
#define N_EDGES 1600000
#define D 128
#define L 3

// ---------------- scratch (device globals; no allocation allowed) ----------
__device__ __align__(16) float g_agg [N_NODES * D];   // mean-aggregated features
__device__ __align__(16) float g_buf0[N_NODES * D];   // ping-pong feature buffers
__device__ __align__(16) float g_buf1[N_NODES * D];
__device__ float    g_inv [N_NODES];       // 1 / max(count,1)
__device__ int      g_cnt [N_NODES];
__device__ int      g_off [N_NODES + 1];   // CSR offsets (by dst)
__device__ int      g_cur [N_NODES];       // fill cursors
__device__ int      g_adj [N_EDGES];       // CSR adjacency: src lists per dst
__device__ unsigned g_minbuf[D];           // monotone-uint min accumulator

// monotone mapping: order-preserving float -> uint
__device__ __forceinline__ unsigned f2mono(float f) {
    unsigned u = __float_as_uint(f);
    return (u & 0x80000000u) ? ~u : (u | 0x80000000u);
}
__device__ __forceinline__ float mono2f(unsigned m) {
    return (m & 0x80000000u) ? __uint_as_float(m ^ 0x80000000u)
                             : __uint_as_float(~m);
}
__device__ __forceinline__ uint32_t f2tf32(float f) {
    uint32_t u;
    asm("cvt.rna.tf32.f32 %0, %1;" : "=r"(u) : "f"(f));
    return u;
}

// ---------------- init ------------------------------------------------------
__global__ void k_init(void) {
    int i = blockIdx.x * blockDim.x + threadIdx.x;
    if (i < N_NODES) g_cnt[i] = 0;
    if (i < D)       g_minbuf[i] = 0xFFFFFFFFu;
}

// ---------------- degree histogram -----------------------------------------
__global__ void k_count(const int* __restrict__ ei) {
    int e = blockIdx.x * blockDim.x + threadIdx.x;
    if (e >= N_EDGES) return;
    atomicAdd(&g_cnt[ei[N_EDGES + e]], 1);
}

// ---------------- single-block exclusive scan -> offsets only ---------------
__global__ void __launch_bounds__(1024) k_scan(void) {
    __shared__ int ssum[1024];
    const int CH = (N_NODES + 1023) / 1024;   // 98
    int tid  = threadIdx.x;
    int base = tid * CH;
    int s = 0;
    for (int i = 0; i < CH; i++) {
        int idx = base + i;
        if (idx < N_NODES) s += g_cnt[idx];
    }
    ssum[tid] = s;
    __syncthreads();
    for (int off = 1; off < 1024; off <<= 1) {
        int v = (tid >= off) ? ssum[tid - off] : 0;
        __syncthreads();
        ssum[tid] += v;
        __syncthreads();
    }
    int run = (tid > 0) ? ssum[tid - 1] : 0;
    for (int i = 0; i < CH; i++) {
        int idx = base + i;
        if (idx < N_NODES) {
            g_off[idx] = run;
            run += g_cnt[idx];
        }
    }
    if (tid == 1023) g_off[N_NODES] = ssum[1023];
}

// ---------------- cursor copy + inverse count (coalesced, parallel) ---------
__global__ void k_prep(void) {
    int i = blockIdx.x * blockDim.x + threadIdx.x;
    if (i >= N_NODES) return;
    g_cur[i] = g_off[i];
    g_inv[i] = 1.0f / fmaxf((float)g_cnt[i], 1.0f);
}

// ---------------- CSR fill ---------------------------------------------------
__global__ void k_fill(const int* __restrict__ ei) {
    int e = blockIdx.x * blockDim.x + threadIdx.x;
    if (e >= N_EDGES) return;
    int src = ei[e];
    int dst = ei[N_EDGES + e];
    int pos = atomicAdd(&g_cur[dst], 1);
    g_adj[pos] = src;
}

// ---------------- per-layer mean gather: one warp per node ------------------
__global__ void __launch_bounds__(256) k_gather(const float* __restrict__ xcur) {
    int wid  = (blockIdx.x * blockDim.x + threadIdx.x) >> 5;
    int lane = threadIdx.x & 31;
    if (wid >= N_NODES) return;
    int node = wid;

    int off0 = g_off[node];
    int off1 = g_off[node + 1];

    float4 acc = make_float4(0.f, 0.f, 0.f, 0.f);
    int i = off0;
    for (; i + 4 <= off1; i += 4) {
        int nb0 = g_adj[i + 0];
        int nb1 = g_adj[i + 1];
        int nb2 = g_adj[i + 2];
        int nb3 = g_adj[i + 3];
        float4 v0 = ((const float4*)(xcur + (long long)nb0 * D))[lane];
        float4 v1 = ((const float4*)(xcur + (long long)nb1 * D))[lane];
        float4 v2 = ((const float4*)(xcur + (long long)nb2 * D))[lane];
        float4 v3 = ((const float4*)(xcur + (long long)nb3 * D))[lane];
        acc.x += v0.x + v1.x + v2.x + v3.x;
        acc.y += v0.y + v1.y + v2.y + v3.y;
        acc.z += v0.z + v1.z + v2.z + v3.z;
        acc.w += v0.w + v1.w + v2.w + v3.w;
    }
    for (; i < off1; i++) {
        int nb = g_adj[i];
        float4 v = ((const float4*)(xcur + (long long)nb * D))[lane];
        acc.x += v.x; acc.y += v.y; acc.z += v.z; acc.w += v.w;
    }
    float s = g_inv[node];
    acc.x *= s; acc.y *= s; acc.z *= s; acc.w *= s;
    ((float4*)(g_agg + (long long)node * D))[lane] = acc;
}

// ---------------- tf32 tensor-core fused SAGE GEMM --------------------------
// Block: 128 nodes x 128 cols, BK=32, 256 threads = 8 warps (4m x 2n).
// Staging: each thread loads one 16-float row-half (4x LDG.128) and writes the
// k-permuted tf32 layout with 4 contiguous STS.128 (perm packs k8 group
// [e0..e7] as [e0,e4,e1,e5][e2,e6,e3,e7]).
// MINF=1: fold column-wise min into epilogue, skip xnext store.
#define AS 36

__device__ __forceinline__ void mma_tf32(float* d, const uint32_t* a,
                                         uint32_t b0, uint32_t b1) {
    asm volatile(
        "mma.sync.aligned.m16n8k8.row.col.f32.tf32.tf32.f32 "
        "{%0,%1,%2,%3}, {%4,%5,%6,%7}, {%8,%9}, {%0,%1,%2,%3};"
        : "+f"(d[0]), "+f"(d[1]), "+f"(d[2]), "+f"(d[3])
        : "r"(a[0]), "r"(a[1]), "r"(a[2]), "r"(a[3]), "r"(b0), "r"(b1));
}

// stage one 16-float contiguous k-run (two k8 groups) into permuted smem
__device__ __forceinline__ void stage16(const float* __restrict__ src,
                                        uint32_t* __restrict__ dstWords) {
    float4 va = ((const float4*)src)[0];   // e0..e3  of group 0
    float4 vb = ((const float4*)src)[1];   // e4..e7  of group 0
    float4 vc = ((const float4*)src)[2];   // e0..e3  of group 1
    float4 vd = ((const float4*)src)[3];   // e4..e7  of group 1
    uint4* d4 = (uint4*)dstWords;
    uint4 w0, w1, w2, w3;
    w0.x = f2tf32(va.x); w0.y = f2tf32(vb.x); w0.z = f2tf32(va.y); w0.w = f2tf32(vb.y);
    w1.x = f2tf32(va.z); w1.y = f2tf32(vb.z); w1.z = f2tf32(va.w); w1.w = f2tf32(vb.w);
    w2.x = f2tf32(vc.x); w2.y = f2tf32(vd.x); w2.z = f2tf32(vc.y); w2.w = f2tf32(vd.y);
    w3.x = f2tf32(vc.z); w3.y = f2tf32(vd.z); w3.z = f2tf32(vc.w); w3.w = f2tf32(vd.w);
    d4[0] = w0; d4[1] = w1; d4[2] = w2; d4[3] = w3;
}

template<int RELU, int MINF>
__global__ void __launch_bounds__(256)
k_gemm(const float* __restrict__ xcur,
       const float* __restrict__ Wl,
       const float* __restrict__ bl,
       const float* __restrict__ Wr,
       float* __restrict__ xnext) {
    __shared__ uint32_t As[128 * AS];
    __shared__ uint32_t Bs[128 * AS];
    __shared__ unsigned sMin[128];

    int tid    = threadIdx.x;
    int wid    = tid >> 5;
    int lane   = tid & 31;
    int g      = lane >> 2;
    int c      = lane & 3;
    int warp_m = wid & 3;
    int warp_n = wid >> 2;
    int blockRow = blockIdx.x * 128;

    if (MINF && tid < 128) sMin[tid] = 0xFFFFFFFFu;

    // staging coordinates: thread handles row r, k-half h (16 floats)
    int srow  = tid >> 1;
    int shalf = tid & 1;

    float acc[2][8][4];
#pragma unroll
    for (int mt = 0; mt < 2; mt++)
#pragma unroll
        for (int nt = 0; nt < 8; nt++)
#pragma unroll
            for (int r = 0; r < 4; r++) acc[mt][nt][r] = 0.f;

    for (int kc = 0; kc < 8; kc++) {
        bool meanRegion = (kc < 4);
        int  kb = meanRegion ? kc * 32 : (kc - 4) * 32;
        const float* Asrc = meanRegion ? g_agg : xcur;
        const float* Wsrc = meanRegion ? Wl : Wr;

        // ---- stage A: row = blockRow + srow (clamped), 16 floats at kb+shalf*16
        {
            int n = blockRow + srow;
            if (n >= N_NODES) n = N_NODES - 1;
            stage16(Asrc + (long long)n * D + kb + shalf * 16,
                    &As[srow * AS + shalf * 16]);
        }
        // ---- stage B: col j = srow, 16 floats at kb+shalf*16
        stage16(Wsrc + (long long)srow * D + kb + shalf * 16,
                &Bs[srow * AS + shalf * 16]);
        __syncthreads();

#pragma unroll
        for (int ks = 0; ks < 4; ks++) {
            uint32_t a[2][4];
#pragma unroll
            for (int mt = 0; mt < 2; mt++) {
                int row = warp_m * 32 + mt * 16 + g;
                uint2 lo = *(uint2*)&As[row * AS + ks * 8 + 2 * c];
                uint2 hi = *(uint2*)&As[(row + 8) * AS + ks * 8 + 2 * c];
                a[mt][0] = lo.x; a[mt][2] = lo.y;
                a[mt][1] = hi.x; a[mt][3] = hi.y;
            }
#pragma unroll
            for (int nt = 0; nt < 8; nt++) {
                int col = warp_n * 64 + nt * 8 + g;
                uint2 b = *(uint2*)&Bs[col * AS + ks * 8 + 2 * c];
                mma_tf32(acc[0][nt], a[0], b.x, b.y);
                mma_tf32(acc[1][nt], a[1], b.x, b.y);
            }
        }
        __syncthreads();
    }

    // ---- epilogue ----
#pragma unroll
    for (int nt = 0; nt < 8; nt++) {
        int col = warp_n * 64 + nt * 8 + 2 * c;
        float b0 = bl[col];
        float b1 = bl[col + 1];
        if (MINF) {
            float m0 = 3.4e38f, m1 = 3.4e38f;
#pragma unroll
            for (int mt = 0; mt < 2; mt++) {
                int row0 = blockRow + warp_m * 32 + mt * 16 + g;
                if (row0 < N_NODES) {
                    m0 = fminf(m0, acc[mt][nt][0] + b0);
                    m1 = fminf(m1, acc[mt][nt][1] + b1);
                }
                if (row0 + 8 < N_NODES) {
                    m0 = fminf(m0, acc[mt][nt][2] + b0);
                    m1 = fminf(m1, acc[mt][nt][3] + b1);
                }
            }
#pragma unroll
            for (int s = 16; s >= 4; s >>= 1) {
                m0 = fminf(m0, __shfl_xor_sync(0xFFFFFFFFu, m0, s));
                m1 = fminf(m1, __shfl_xor_sync(0xFFFFFFFFu, m1, s));
            }
            if (g == 0) {
                atomicMin(&sMin[col],     f2mono(m0));
                atomicMin(&sMin[col + 1], f2mono(m1));
            }
        } else {
#pragma unroll
            for (int mt = 0; mt < 2; mt++) {
                int row0 = blockRow + warp_m * 32 + mt * 16 + g;
                float v0 = acc[mt][nt][0] + b0;
                float v1 = acc[mt][nt][1] + b1;
                float v2 = acc[mt][nt][2] + b0;
                float v3 = acc[mt][nt][3] + b1;
                if (RELU) {
                    v0 = fmaxf(v0, 0.f); v1 = fmaxf(v1, 0.f);
                    v2 = fmaxf(v2, 0.f); v3 = fmaxf(v3, 0.f);
                }
                if (row0 < N_NODES)
                    *(float2*)(xnext + (long long)row0 * D + col) = make_float2(v0, v1);
                if (row0 + 8 < N_NODES)
                    *(float2*)(xnext + (long long)(row0 + 8) * D + col) = make_float2(v2, v3);
            }
        }
    }

    if (MINF) {
        __syncthreads();
        if (tid < 128) atomicMin(&g_minbuf[tid], sMin[tid]);
    }
}

// ---------------- final writeout --------------------------------------------
__global__ void k_writeout(float* __restrict__ out) {
    int j = threadIdx.x;
    out[j] = mono2f(g_minbuf[j]);
}

// ---------------- launch ----------------------------------------------------
extern "C" void kernel_launch(void* const* d_in, const int* in_sizes, int n_in,
                              void* d_out, int out_size) {
    const float* x  = (const float*)d_in[0];
    const int*   ei = (const int*)d_in[1];       // int32 edge index
    const float* Wl = (const float*)d_in[2];     // [L,D,D]
    const float* bl = (const float*)d_in[3];     // [L,D]
    const float* Wr = (const float*)d_in[4];     // [L,D,D]
    float*       out = (float*)d_out;

    // ---- CSR build (once per launch)
    k_init <<<(N_NODES + 255) / 256, 256>>>();
    k_count<<<(N_EDGES + 255) / 256, 256>>>(ei);
    k_scan <<<1, 1024>>>();
    k_prep <<<(N_NODES + 255) / 256, 256>>>();
    k_fill <<<(N_EDGES + 255) / 256, 256>>>(ei);

    float* bufs[2];
    cudaGetSymbolAddress((void**)&bufs[0], g_buf0);
    cudaGetSymbolAddress((void**)&bufs[1], g_buf1);

    const int gemmBlocks   = (N_NODES + 127) / 128;        // 782
    const int gatherBlocks = (N_NODES + 7) / 8;            // 12500 (8 warps/block)

    const float* cur = x;
    for (int layer = 0; layer < L; layer++) {
        float* nxt = bufs[layer & 1];
        k_gather<<<gatherBlocks, 256>>>(cur);
        const float* wl = Wl + (long long)layer * D * D;
        const float* wr = Wr + (long long)layer * D * D;
        const float* b  = bl + (long long)layer * D;
        if (layer < L - 1)
            k_gemm<1,0><<<gemmBlocks, 256>>>(cur, wl, b, wr, nxt);
        else
            k_gemm<0,1><<<gemmBlocks, 256>>>(cur, wl, b, wr, nxt);
        cur = nxt;
    }

    k_writeout<<<1, D>>>(out);
}

// round 8
// speedup vs baseline: 2.2678x; 1.6253x over previous
#include <cuda_runtime.h>
#include <cuda_fp16.h>
#include <cstdint>

#define N_NODES 100000
#define N_EDGES 1600000
#define D 128
#define L 3
#define SCAN_BLKS ((N_NODES + 1023) / 1024)   // 98

// ---------------- scratch (device globals; no allocation allowed) ----------
__device__ __align__(16) __half g_hx  [N_NODES * D];  // fp16 input features
__device__ __align__(16) __half g_hagg[N_NODES * D];  // fp16 mean-aggregated
__device__ __align__(16) __half g_hb0 [N_NODES * D];  // fp16 ping-pong buffers
__device__ __align__(16) __half g_hb1 [N_NODES * D];
__device__ int      g_cnt [N_NODES];
__device__ int      g_off [N_NODES + 1];
__device__ int      g_cur [N_NODES];
__device__ int      g_adj [N_EDGES];
__device__ int      g_bsum[128];
__device__ unsigned g_minbuf[D];

// monotone mapping: order-preserving float -> uint
__device__ __forceinline__ unsigned f2mono(float f) {
    unsigned u = __float_as_uint(f);
    return (u & 0x80000000u) ? ~u : (u | 0x80000000u);
}
__device__ __forceinline__ float mono2f(unsigned m) {
    return (m & 0x80000000u) ? __uint_as_float(m ^ 0x80000000u)
                             : __uint_as_float(~m);
}
__device__ __forceinline__ uint32_t packh2(float a, float b) {
    __half2 h = __floats2half2_rn(a, b);
    return *(uint32_t*)&h;
}

// ---------------- degree histogram -----------------------------------------
__global__ void k_count(const int* __restrict__ ei) {
    int e = blockIdx.x * blockDim.x + threadIdx.x;
    if (e >= N_EDGES) return;
    atomicAdd(&g_cnt[ei[N_EDGES + e]], 1);
}

// ---------------- hierarchical scan -----------------------------------------
__global__ void __launch_bounds__(1024) k_scanA(void) {
    __shared__ int s[1024];
    int t = threadIdx.x;
    int i = blockIdx.x * 1024 + t;
    int v = (i < N_NODES) ? g_cnt[i] : 0;
    s[t] = v;
    __syncthreads();
    for (int o = 1; o < 1024; o <<= 1) {
        int u = (t >= o) ? s[t - o] : 0;
        __syncthreads();
        s[t] += u;
        __syncthreads();
    }
    if (i < N_NODES) g_off[i] = s[t] - v;        // block-local exclusive
    if (t == 1023)   g_bsum[blockIdx.x] = s[t];  // block total
}

__global__ void k_scanB(void) {
    __shared__ int s[128];
    int t = threadIdx.x;
    int v = (t < SCAN_BLKS) ? g_bsum[t] : 0;
    s[t] = v;
    __syncthreads();
    for (int o = 1; o < 128; o <<= 1) {
        int u = (t >= o) ? s[t - o] : 0;
        __syncthreads();
        s[t] += u;
        __syncthreads();
    }
    if (t < SCAN_BLKS) g_bsum[t] = s[t] - v;     // exclusive block base
    if (t == 127)      g_off[N_NODES] = s[127];  // total = N_EDGES
}

__global__ void k_scanC(void) {
    int i = blockIdx.x * blockDim.x + threadIdx.x;
    if (i >= N_NODES) return;
    int o = g_off[i] + g_bsum[i >> 10];
    g_off[i] = o;
    g_cur[i] = o;
}

// ---------------- CSR fill ---------------------------------------------------
__global__ void k_fill(const int* __restrict__ ei) {
    int e = blockIdx.x * blockDim.x + threadIdx.x;
    if (e >= N_EDGES) return;
    int src = ei[e];
    int dst = ei[N_EDGES + e];
    int pos = atomicAdd(&g_cur[dst], 1);
    g_adj[pos] = src;
}

// ---------------- f32 -> fp16 input conversion ------------------------------
__global__ void k_tohalf(const float* __restrict__ x) {
    int i = blockIdx.x * blockDim.x + threadIdx.x;
    if (i >= N_NODES * D / 2) return;
    float2 v = ((const float2*)x)[i];
    ((__half2*)g_hx)[i] = __floats2half2_rn(v.x, v.y);
}

// ---------------- per-layer mean gather (fp16): one warp per node -----------
__global__ void __launch_bounds__(256) k_gather(const __half* __restrict__ xcur) {
    int wid  = (blockIdx.x * blockDim.x + threadIdx.x) >> 5;
    int lane = threadIdx.x & 31;
    if (wid >= N_NODES) return;
    int node = wid;

    int off0 = g_off[node];
    int off1 = g_off[node + 1];

    float4 acc = make_float4(0.f, 0.f, 0.f, 0.f);
    int i = off0;
    for (; i + 4 <= off1; i += 4) {
        int nb0 = g_adj[i + 0];
        int nb1 = g_adj[i + 1];
        int nb2 = g_adj[i + 2];
        int nb3 = g_adj[i + 3];
        uint2 u0 = ((const uint2*)(xcur + (long long)nb0 * D))[lane];
        uint2 u1 = ((const uint2*)(xcur + (long long)nb1 * D))[lane];
        uint2 u2 = ((const uint2*)(xcur + (long long)nb2 * D))[lane];
        uint2 u3 = ((const uint2*)(xcur + (long long)nb3 * D))[lane];
        float2 a0 = __half22float2(*(__half2*)&u0.x), b0 = __half22float2(*(__half2*)&u0.y);
        float2 a1 = __half22float2(*(__half2*)&u1.x), b1 = __half22float2(*(__half2*)&u1.y);
        float2 a2 = __half22float2(*(__half2*)&u2.x), b2 = __half22float2(*(__half2*)&u2.y);
        float2 a3 = __half22float2(*(__half2*)&u3.x), b3 = __half22float2(*(__half2*)&u3.y);
        acc.x += a0.x + a1.x + a2.x + a3.x;
        acc.y += a0.y + a1.y + a2.y + a3.y;
        acc.z += b0.x + b1.x + b2.x + b3.x;
        acc.w += b0.y + b1.y + b2.y + b3.y;
    }
    for (; i < off1; i++) {
        int nb = g_adj[i];
        uint2 u = ((const uint2*)(xcur + (long long)nb * D))[lane];
        float2 a = __half22float2(*(__half2*)&u.x), b = __half22float2(*(__half2*)&u.y);
        acc.x += a.x; acc.y += a.y; acc.z += b.x; acc.w += b.y;
    }
    float s = 1.0f / fmaxf((float)(off1 - off0), 1.0f);
    uint2 o;
    o.x = packh2(acc.x * s, acc.y * s);
    o.y = packh2(acc.z * s, acc.w * s);
    ((uint2*)(g_hagg + (long long)node * D))[lane] = o;
}

// ---------------- fp16 tensor-core fused SAGE GEMM --------------------------
// Block 128x128, BK=32, 256 threads = 8 warps (4m x 2n), warp tile 32x64.
// mma.m16n8k16 f16xf16->f32. Permuted smem (pair p, p+4 adjacent), row
// stride 24 uint32 words -> conflict-light uint2 fragment loads.
#define AS2 24

__device__ __forceinline__ void mma_f16(float* d, const uint32_t* a,
                                        uint32_t b0, uint32_t b1) {
    asm volatile(
        "mma.sync.aligned.m16n8k16.row.col.f32.f16.f16.f32 "
        "{%0,%1,%2,%3}, {%4,%5,%6,%7}, {%8,%9}, {%0,%1,%2,%3};"
        : "+f"(d[0]), "+f"(d[1]), "+f"(d[2]), "+f"(d[3])
        : "r"(a[0]), "r"(a[1]), "r"(a[2]), "r"(a[3]), "r"(b0), "r"(b1));
}

// stage 16 contiguous halves (one k16 group) permuted: [p0,p4,p1,p5][p2,p6,p3,p7]
__device__ __forceinline__ void stageA(const __half* __restrict__ src,
                                       uint32_t* __restrict__ dst) {
    uint4 q0 = ((const uint4*)src)[0];   // pairs p0..p3
    uint4 q1 = ((const uint4*)src)[1];   // pairs p4..p7
    uint4 w0 = make_uint4(q0.x, q1.x, q0.y, q1.y);
    uint4 w1 = make_uint4(q0.z, q1.z, q0.w, q1.w);
    ((uint4*)dst)[0] = w0;
    ((uint4*)dst)[1] = w1;
}
// stage 16 contiguous floats (one k16 group), convert to fp16, permuted
__device__ __forceinline__ void stageB(const float* __restrict__ src,
                                       uint32_t* __restrict__ dst) {
    float4 a = ((const float4*)src)[0];
    float4 b = ((const float4*)src)[1];
    float4 c = ((const float4*)src)[2];
    float4 d = ((const float4*)src)[3];
    uint32_t p0 = packh2(a.x, a.y), p1 = packh2(a.z, a.w);
    uint32_t p2 = packh2(b.x, b.y), p3 = packh2(b.z, b.w);
    uint32_t p4 = packh2(c.x, c.y), p5 = packh2(c.z, c.w);
    uint32_t p6 = packh2(d.x, d.y), p7 = packh2(d.z, d.w);
    uint4 w0 = make_uint4(p0, p4, p1, p5);
    uint4 w1 = make_uint4(p2, p6, p3, p7);
    ((uint4*)dst)[0] = w0;
    ((uint4*)dst)[1] = w1;
}

template<int RELU, int MINF>
__global__ void __launch_bounds__(256)
k_gemm(const __half* __restrict__ xcur,
       const float* __restrict__ Wl,
       const float* __restrict__ bl,
       const float* __restrict__ Wr,
       __half* __restrict__ xnext) {
    __shared__ uint32_t As[128 * AS2];
    __shared__ uint32_t Bs[128 * AS2];
    __shared__ unsigned sMin[128];

    int tid    = threadIdx.x;
    int wid    = tid >> 5;
    int lane   = tid & 31;
    int g      = lane >> 2;
    int c      = lane & 3;
    int warp_m = wid & 3;
    int warp_n = wid >> 2;
    int blockRow = blockIdx.x * 128;

    if (MINF && tid < 128) sMin[tid] = 0xFFFFFFFFu;

    int srow  = tid >> 1;        // staged row / weight col
    int shalf = tid & 1;         // which k16 group of the 32-k chunk

    float acc[2][8][4];
#pragma unroll
    for (int mt = 0; mt < 2; mt++)
#pragma unroll
        for (int nt = 0; nt < 8; nt++)
#pragma unroll
            for (int r = 0; r < 4; r++) acc[mt][nt][r] = 0.f;

    for (int kc = 0; kc < 8; kc++) {
        bool meanRegion = (kc < 4);
        int  kb = meanRegion ? kc * 32 : (kc - 4) * 32;
        const __half* Asrc = meanRegion ? g_hagg : xcur;
        const float*  Wsrc = meanRegion ? Wl : Wr;

        {
            int n = blockRow + srow;
            if (n >= N_NODES) n = N_NODES - 1;
            stageA(Asrc + (long long)n * D + kb + shalf * 16,
                   &As[srow * AS2 + shalf * 8]);
        }
        stageB(Wsrc + (long long)srow * D + kb + shalf * 16,
               &Bs[srow * AS2 + shalf * 8]);
        __syncthreads();

#pragma unroll
        for (int ks = 0; ks < 2; ks++) {
            uint32_t a[2][4];
#pragma unroll
            for (int mt = 0; mt < 2; mt++) {
                int row = warp_m * 32 + mt * 16 + g;
                uint2 lo = *(uint2*)&As[row * AS2 + ks * 8 + 2 * c];
                uint2 hi = *(uint2*)&As[(row + 8) * AS2 + ks * 8 + 2 * c];
                a[mt][0] = lo.x; a[mt][1] = hi.x;
                a[mt][2] = lo.y; a[mt][3] = hi.y;
            }
#pragma unroll
            for (int nt = 0; nt < 8; nt++) {
                int col = warp_n * 64 + nt * 8 + g;
                uint2 b = *(uint2*)&Bs[col * AS2 + ks * 8 + 2 * c];
                mma_f16(acc[0][nt], a[0], b.x, b.y);
                mma_f16(acc[1][nt], a[1], b.x, b.y);
            }
        }
        __syncthreads();
    }

    // ---- epilogue ----
#pragma unroll
    for (int nt = 0; nt < 8; nt++) {
        int col = warp_n * 64 + nt * 8 + 2 * c;
        float b0 = bl[col];
        float b1 = bl[col + 1];
        if (MINF) {
            float m0 = 3.4e38f, m1 = 3.4e38f;
#pragma unroll
            for (int mt = 0; mt < 2; mt++) {
                int row0 = blockRow + warp_m * 32 + mt * 16 + g;
                if (row0 < N_NODES) {
                    m0 = fminf(m0, acc[mt][nt][0] + b0);
                    m1 = fminf(m1, acc[mt][nt][1] + b1);
                }
                if (row0 + 8 < N_NODES) {
                    m0 = fminf(m0, acc[mt][nt][2] + b0);
                    m1 = fminf(m1, acc[mt][nt][3] + b1);
                }
            }
#pragma unroll
            for (int s = 16; s >= 4; s >>= 1) {
                m0 = fminf(m0, __shfl_xor_sync(0xFFFFFFFFu, m0, s));
                m1 = fminf(m1, __shfl_xor_sync(0xFFFFFFFFu, m1, s));
            }
            if (g == 0) {
                atomicMin(&sMin[col],     f2mono(m0));
                atomicMin(&sMin[col + 1], f2mono(m1));
            }
        } else {
#pragma unroll
            for (int mt = 0; mt < 2; mt++) {
                int row0 = blockRow + warp_m * 32 + mt * 16 + g;
                float v0 = acc[mt][nt][0] + b0;
                float v1 = acc[mt][nt][1] + b1;
                float v2 = acc[mt][nt][2] + b0;
                float v3 = acc[mt][nt][3] + b1;
                if (RELU) {
                    v0 = fmaxf(v0, 0.f); v1 = fmaxf(v1, 0.f);
                    v2 = fmaxf(v2, 0.f); v3 = fmaxf(v3, 0.f);
                }
                if (row0 < N_NODES)
                    ((uint32_t*)(xnext + (long long)row0 * D))[col >> 1] = packh2(v0, v1);
                if (row0 + 8 < N_NODES)
                    ((uint32_t*)(xnext + (long long)(row0 + 8) * D))[col >> 1] = packh2(v2, v3);
            }
        }
    }

    if (MINF) {
        __syncthreads();
        if (tid < 128) atomicMin(&g_minbuf[tid], sMin[tid]);
    }
}

// ---------------- final writeout --------------------------------------------
__global__ void k_writeout(float* __restrict__ out) {
    int j = threadIdx.x;
    out[j] = mono2f(g_minbuf[j]);
}

// ---------------- launch ----------------------------------------------------
extern "C" void kernel_launch(void* const* d_in, const int* in_sizes, int n_in,
                              void* d_out, int out_size) {
    const float* x  = (const float*)d_in[0];
    const int*   ei = (const int*)d_in[1];       // int32 edge index
    const float* Wl = (const float*)d_in[2];     // [L,D,D]
    const float* bl = (const float*)d_in[3];     // [L,D]
    const float* Wr = (const float*)d_in[4];     // [L,D,D]
    float*       out = (float*)d_out;

    void *p_cnt, *p_min;
    cudaGetSymbolAddress(&p_cnt, g_cnt);
    cudaGetSymbolAddress(&p_min, g_minbuf);
    cudaMemsetAsync(p_cnt, 0, N_NODES * sizeof(int));
    cudaMemsetAsync(p_min, 0xFF, D * sizeof(unsigned));

    // ---- CSR build + fp16 convert
    k_count <<<(N_EDGES + 255) / 256, 256>>>(ei);
    k_scanA <<<SCAN_BLKS, 1024>>>();
    k_scanB <<<1, 128>>>();
    k_scanC <<<(N_NODES + 255) / 256, 256>>>();
    k_fill  <<<(N_EDGES + 255) / 256, 256>>>(ei);
    k_tohalf<<<(N_NODES * D / 2 + 255) / 256, 256>>>(x);

    __half* bufs[2];
    cudaGetSymbolAddress((void**)&bufs[0], g_hb0);
    cudaGetSymbolAddress((void**)&bufs[1], g_hb1);
    __half* hx;
    cudaGetSymbolAddress((void**)&hx, g_hx);

    const int gemmBlocks   = (N_NODES + 127) / 128;   // 782
    const int gatherBlocks = (N_NODES + 7) / 8;       // 12500

    const __half* cur = hx;
    for (int layer = 0; layer < L; layer++) {
        __half* nxt = bufs[layer & 1];
        k_gather<<<gatherBlocks, 256>>>(cur);
        const float* wl = Wl + (long long)layer * D * D;
        const float* wr = Wr + (long long)layer * D * D;
        const float* b  = bl + (long long)layer * D;
        if (layer < L - 1)
            k_gemm<1,0><<<gemmBlocks, 256>>>(cur, wl, b, wr, nxt);
        else
            k_gemm<0,1><<<gemmBlocks, 256>>>(cur, wl, b, wr, nxt);
        cur = nxt;
    }

    k_writeout<<<1, D>>>(out);
}

// round 9
// speedup vs baseline: 2.4400x; 1.0759x over previous
#include <cuda_runtime.h>
#include <cuda_fp16.h>
#include <cstdint>

#define N_NODES 100000
#define N_EDGES 1600000
#define D 128
#define L 3
#define SCAN_BLKS ((N_NODES + 1023) / 1024)   // 98

// ---------------- scratch (device globals; no allocation allowed) ----------
__device__ __align__(16) __half g_hx  [N_NODES * D];  // fp16 input features
__device__ __align__(16) __half g_hagg[N_NODES * D];  // fp16 mean-aggregated
__device__ __align__(16) __half g_hb0 [N_NODES * D];  // fp16 ping-pong buffers
__device__ __align__(16) __half g_hb1 [N_NODES * D];
__device__ __align__(16) __half g_hwl [L * D * D];    // fp16 weights (lin_l)
__device__ __align__(16) __half g_hwr [L * D * D];    // fp16 weights (lin_r)
__device__ int      g_cnt [N_NODES];
__device__ int      g_off [N_NODES + 1];
__device__ int      g_cur [N_NODES];
__device__ int      g_adj [N_EDGES];
__device__ int      g_bsum[128];
__device__ unsigned g_minbuf[D];

// monotone mapping: order-preserving float -> uint
__device__ __forceinline__ unsigned f2mono(float f) {
    unsigned u = __float_as_uint(f);
    return (u & 0x80000000u) ? ~u : (u | 0x80000000u);
}
__device__ __forceinline__ float mono2f(unsigned m) {
    return (m & 0x80000000u) ? __uint_as_float(m ^ 0x80000000u)
                             : __uint_as_float(~m);
}
__device__ __forceinline__ uint32_t packh2(float a, float b) {
    __half2 h = __floats2half2_rn(a, b);
    return *(uint32_t*)&h;
}

// ---------------- degree histogram -----------------------------------------
__global__ void k_count(const int* __restrict__ ei) {
    int e = blockIdx.x * blockDim.x + threadIdx.x;
    if (e >= N_EDGES) return;
    atomicAdd(&g_cnt[ei[N_EDGES + e]], 1);
}

// ---------------- hierarchical scan -----------------------------------------
__global__ void __launch_bounds__(1024) k_scanA(void) {
    __shared__ int s[1024];
    int t = threadIdx.x;
    int i = blockIdx.x * 1024 + t;
    int v = (i < N_NODES) ? g_cnt[i] : 0;
    s[t] = v;
    __syncthreads();
    for (int o = 1; o < 1024; o <<= 1) {
        int u = (t >= o) ? s[t - o] : 0;
        __syncthreads();
        s[t] += u;
        __syncthreads();
    }
    if (i < N_NODES) g_off[i] = s[t] - v;
    if (t == 1023)   g_bsum[blockIdx.x] = s[t];
}

__global__ void k_scanB(void) {
    __shared__ int s[128];
    int t = threadIdx.x;
    int v = (t < SCAN_BLKS) ? g_bsum[t] : 0;
    s[t] = v;
    __syncthreads();
    for (int o = 1; o < 128; o <<= 1) {
        int u = (t >= o) ? s[t - o] : 0;
        __syncthreads();
        s[t] += u;
        __syncthreads();
    }
    if (t < SCAN_BLKS) g_bsum[t] = s[t] - v;
    if (t == 127)      g_off[N_NODES] = s[127];
}

__global__ void k_scanC(void) {
    int i = blockIdx.x * blockDim.x + threadIdx.x;
    if (i >= N_NODES) return;
    int o = g_off[i] + g_bsum[i >> 10];
    g_off[i] = o;
    g_cur[i] = o;
}

// ---------------- CSR fill ---------------------------------------------------
__global__ void k_fill(const int* __restrict__ ei) {
    int e = blockIdx.x * blockDim.x + threadIdx.x;
    if (e >= N_EDGES) return;
    int src = ei[e];
    int dst = ei[N_EDGES + e];
    int pos = atomicAdd(&g_cur[dst], 1);
    g_adj[pos] = src;
}

// ---------------- f32 -> fp16 conversions ------------------------------------
__global__ void k_tohalf(const float* __restrict__ x) {
    int i = blockIdx.x * blockDim.x + threadIdx.x;
    if (i >= N_NODES * D / 2) return;
    float2 v = ((const float2*)x)[i];
    ((__half2*)g_hx)[i] = __floats2half2_rn(v.x, v.y);
}

__global__ void k_wconv(const float* __restrict__ Wl,
                        const float* __restrict__ Wr) {
    int i = blockIdx.x * blockDim.x + threadIdx.x;
    const int HALF2S = L * D * D / 2;        // 24576 per matrix
    if (i < HALF2S) {
        float2 v = ((const float2*)Wl)[i];
        ((__half2*)g_hwl)[i] = __floats2half2_rn(v.x, v.y);
    } else if (i < 2 * HALF2S) {
        float2 v = ((const float2*)Wr)[i - HALF2S];
        ((__half2*)g_hwr)[i - HALF2S] = __floats2half2_rn(v.x, v.y);
    }
}

// ---------------- per-layer mean gather (fp16): one warp per node -----------
__global__ void __launch_bounds__(256) k_gather(const __half* __restrict__ xcur) {
    int wid  = (blockIdx.x * blockDim.x + threadIdx.x) >> 5;
    int lane = threadIdx.x & 31;
    if (wid >= N_NODES) return;
    int node = wid;

    int off0 = g_off[node];
    int off1 = g_off[node + 1];

    float4 acc = make_float4(0.f, 0.f, 0.f, 0.f);
    int i = off0;
    for (; i + 4 <= off1; i += 4) {
        int nb0 = g_adj[i + 0];
        int nb1 = g_adj[i + 1];
        int nb2 = g_adj[i + 2];
        int nb3 = g_adj[i + 3];
        uint2 u0 = ((const uint2*)(xcur + (long long)nb0 * D))[lane];
        uint2 u1 = ((const uint2*)(xcur + (long long)nb1 * D))[lane];
        uint2 u2 = ((const uint2*)(xcur + (long long)nb2 * D))[lane];
        uint2 u3 = ((const uint2*)(xcur + (long long)nb3 * D))[lane];
        float2 a0 = __half22float2(*(__half2*)&u0.x), b0 = __half22float2(*(__half2*)&u0.y);
        float2 a1 = __half22float2(*(__half2*)&u1.x), b1 = __half22float2(*(__half2*)&u1.y);
        float2 a2 = __half22float2(*(__half2*)&u2.x), b2 = __half22float2(*(__half2*)&u2.y);
        float2 a3 = __half22float2(*(__half2*)&u3.x), b3 = __half22float2(*(__half2*)&u3.y);
        acc.x += a0.x + a1.x + a2.x + a3.x;
        acc.y += a0.y + a1.y + a2.y + a3.y;
        acc.z += b0.x + b1.x + b2.x + b3.x;
        acc.w += b0.y + b1.y + b2.y + b3.y;
    }
    for (; i < off1; i++) {
        int nb = g_adj[i];
        uint2 u = ((const uint2*)(xcur + (long long)nb * D))[lane];
        float2 a = __half22float2(*(__half2*)&u.x), b = __half22float2(*(__half2*)&u.y);
        acc.x += a.x; acc.y += a.y; acc.z += b.x; acc.w += b.y;
    }
    float s = 1.0f / fmaxf((float)(off1 - off0), 1.0f);
    uint2 o;
    o.x = packh2(acc.x * s, acc.y * s);
    o.y = packh2(acc.z * s, acc.w * s);
    ((uint2*)(g_hagg + (long long)node * D))[lane] = o;
}

// ---------------- fp16 tensor-core fused SAGE GEMM (pipelined) ---------------
// Block 128x128, BK=32, 256 threads = 8 warps (4m x 2n), warp tile 32x64.
// mma.m16n8k16. Double-buffered smem; next-chunk LDGs issued before MMAs,
// permute+store after, one __syncthreads per chunk.
#define AS2 24
#define TILE_W (128 * AS2)   // words per matrix tile

__device__ __forceinline__ void mma_f16(float* d, const uint32_t* a,
                                        uint32_t b0, uint32_t b1) {
    asm volatile(
        "mma.sync.aligned.m16n8k16.row.col.f32.f16.f16.f32 "
        "{%0,%1,%2,%3}, {%4,%5,%6,%7}, {%8,%9}, {%0,%1,%2,%3};"
        : "+f"(d[0]), "+f"(d[1]), "+f"(d[2]), "+f"(d[3])
        : "r"(a[0]), "r"(a[1]), "r"(a[2]), "r"(a[3]), "r"(b0), "r"(b1));
}

struct R16 { uint4 a, b; };     // 16 halves = one k16 group

__device__ __forceinline__ R16 load16(const __half* __restrict__ src) {
    R16 r;
    r.a = ((const uint4*)src)[0];
    r.b = ((const uint4*)src)[1];
    return r;
}
// permuted store: [p0,p4,p1,p5][p2,p6,p3,p7]
__device__ __forceinline__ void store16(uint32_t* __restrict__ dst, R16 r) {
    ((uint4*)dst)[0] = make_uint4(r.a.x, r.b.x, r.a.y, r.b.y);
    ((uint4*)dst)[1] = make_uint4(r.a.z, r.b.z, r.a.w, r.b.w);
}

template<int RELU, int MINF>
__global__ void __launch_bounds__(256)
k_gemm(const __half* __restrict__ xcur,
       const __half* __restrict__ wl,
       const float*  __restrict__ bl,
       const __half* __restrict__ wr,
       __half* __restrict__ xnext) {
    extern __shared__ uint32_t smem[];
    uint32_t* AsBuf[2] = { smem,              smem + 2 * TILE_W };
    uint32_t* BsBuf[2] = { smem + TILE_W,     smem + 3 * TILE_W };
    unsigned* sMin = (unsigned*)(smem + 4 * TILE_W);

    int tid    = threadIdx.x;
    int wid    = tid >> 5;
    int lane   = tid & 31;
    int g      = lane >> 2;
    int c      = lane & 3;
    int warp_m = wid & 3;
    int warp_n = wid >> 2;
    int blockRow = blockIdx.x * 128;

    if (MINF && tid < 128) sMin[tid] = 0xFFFFFFFFu;

    int srow  = tid >> 1;        // staged row / weight col
    int shalf = tid & 1;         // which k16 group of the 32-k chunk
    int arow  = blockRow + srow;
    if (arow >= N_NODES) arow = N_NODES - 1;

    float acc[2][8][4];
#pragma unroll
    for (int mt = 0; mt < 2; mt++)
#pragma unroll
        for (int nt = 0; nt < 8; nt++)
#pragma unroll
            for (int r = 0; r < 4; r++) acc[mt][nt][r] = 0.f;

    // chunk kc: A source = (kc<4 ? g_hagg : xcur) at kb=(kc&3)*32
    //           B source = (kc<4 ? wl : wr)
    const __half* aBase0 = g_hagg + (long long)arow * D + shalf * 16;
    const __half* aBase1 = xcur   + (long long)arow * D + shalf * 16;
    const __half* bBase0 = wl + (long long)srow * D + shalf * 16;
    const __half* bBase1 = wr + (long long)srow * D + shalf * 16;

    // prefetch chunk 0
    R16 ra = load16(aBase0);
    R16 rb = load16(bBase0);
    store16(&AsBuf[0][srow * AS2 + shalf * 8], ra);
    store16(&BsBuf[0][srow * AS2 + shalf * 8], rb);
    __syncthreads();

    for (int kc = 0; kc < 8; kc++) {
        int cb = kc & 1;
        // issue next chunk's loads before MMAs
        if (kc < 7) {
            int nk = kc + 1;
            int kb = (nk & 3) * 32;
            ra = load16((nk < 4 ? aBase0 : aBase1) + kb);
            rb = load16((nk < 4 ? bBase0 : bBase1) + kb);
        }

        uint32_t* As = AsBuf[cb];
        uint32_t* Bs = BsBuf[cb];
#pragma unroll
        for (int ks = 0; ks < 2; ks++) {
            uint32_t a[2][4];
#pragma unroll
            for (int mt = 0; mt < 2; mt++) {
                int row = warp_m * 32 + mt * 16 + g;
                uint2 lo = *(uint2*)&As[row * AS2 + ks * 8 + 2 * c];
                uint2 hi = *(uint2*)&As[(row + 8) * AS2 + ks * 8 + 2 * c];
                a[mt][0] = lo.x; a[mt][1] = hi.x;
                a[mt][2] = lo.y; a[mt][3] = hi.y;
            }
#pragma unroll
            for (int nt = 0; nt < 8; nt++) {
                int col = warp_n * 64 + nt * 8 + g;
                uint2 b = *(uint2*)&Bs[col * AS2 + ks * 8 + 2 * c];
                mma_f16(acc[0][nt], a[0], b.x, b.y);
                mma_f16(acc[1][nt], a[1], b.x, b.y);
            }
        }

        if (kc < 7) {
            int nb = cb ^ 1;
            store16(&AsBuf[nb][srow * AS2 + shalf * 8], ra);
            store16(&BsBuf[nb][srow * AS2 + shalf * 8], rb);
            __syncthreads();
        }
    }

    // ---- epilogue ----
#pragma unroll
    for (int nt = 0; nt < 8; nt++) {
        int col = warp_n * 64 + nt * 8 + 2 * c;
        float b0 = bl[col];
        float b1 = bl[col + 1];
        if (MINF) {
            float m0 = 3.4e38f, m1 = 3.4e38f;
#pragma unroll
            for (int mt = 0; mt < 2; mt++) {
                int row0 = blockRow + warp_m * 32 + mt * 16 + g;
                if (row0 < N_NODES) {
                    m0 = fminf(m0, acc[mt][nt][0] + b0);
                    m1 = fminf(m1, acc[mt][nt][1] + b1);
                }
                if (row0 + 8 < N_NODES) {
                    m0 = fminf(m0, acc[mt][nt][2] + b0);
                    m1 = fminf(m1, acc[mt][nt][3] + b1);
                }
            }
#pragma unroll
            for (int s = 16; s >= 4; s >>= 1) {
                m0 = fminf(m0, __shfl_xor_sync(0xFFFFFFFFu, m0, s));
                m1 = fminf(m1, __shfl_xor_sync(0xFFFFFFFFu, m1, s));
            }
            if (g == 0) {
                atomicMin(&sMin[col],     f2mono(m0));
                atomicMin(&sMin[col + 1], f2mono(m1));
            }
        } else {
#pragma unroll
            for (int mt = 0; mt < 2; mt++) {
                int row0 = blockRow + warp_m * 32 + mt * 16 + g;
                float v0 = acc[mt][nt][0] + b0;
                float v1 = acc[mt][nt][1] + b1;
                float v2 = acc[mt][nt][2] + b0;
                float v3 = acc[mt][nt][3] + b1;
                if (RELU) {
                    v0 = fmaxf(v0, 0.f); v1 = fmaxf(v1, 0.f);
                    v2 = fmaxf(v2, 0.f); v3 = fmaxf(v3, 0.f);
                }
                if (row0 < N_NODES)
                    ((uint32_t*)(xnext + (long long)row0 * D))[col >> 1] = packh2(v0, v1);
                if (row0 + 8 < N_NODES)
                    ((uint32_t*)(xnext + (long long)(row0 + 8) * D))[col >> 1] = packh2(v2, v3);
            }
        }
    }

    if (MINF) {
        __syncthreads();
        if (tid < 128) atomicMin(&g_minbuf[tid], sMin[tid]);
    }
}

#define GEMM_SMEM ((4 * TILE_W + 128) * 4)   // 49664 bytes

// ---------------- final writeout --------------------------------------------
__global__ void k_writeout(float* __restrict__ out) {
    int j = threadIdx.x;
    out[j] = mono2f(g_minbuf[j]);
}

// ---------------- launch ----------------------------------------------------
extern "C" void kernel_launch(void* const* d_in, const int* in_sizes, int n_in,
                              void* d_out, int out_size) {
    const float* x  = (const float*)d_in[0];
    const int*   ei = (const int*)d_in[1];       // int32 edge index
    const float* Wl = (const float*)d_in[2];     // [L,D,D]
    const float* bl = (const float*)d_in[3];     // [L,D]
    const float* Wr = (const float*)d_in[4];     // [L,D,D]
    float*       out = (float*)d_out;

    cudaFuncSetAttribute(k_gemm<1,0>, cudaFuncAttributeMaxDynamicSharedMemorySize, GEMM_SMEM);
    cudaFuncSetAttribute(k_gemm<0,1>, cudaFuncAttributeMaxDynamicSharedMemorySize, GEMM_SMEM);

    void *p_cnt, *p_min;
    cudaGetSymbolAddress(&p_cnt, g_cnt);
    cudaGetSymbolAddress(&p_min, g_minbuf);
    cudaMemsetAsync(p_cnt, 0, N_NODES * sizeof(int));
    cudaMemsetAsync(p_min, 0xFF, D * sizeof(unsigned));

    // ---- CSR build + fp16 conversions
    k_count <<<(N_EDGES + 255) / 256, 256>>>(ei);
    k_scanA <<<SCAN_BLKS, 1024>>>();
    k_scanB <<<1, 128>>>();
    k_scanC <<<(N_NODES + 255) / 256, 256>>>();
    k_fill  <<<(N_EDGES + 255) / 256, 256>>>(ei);
    k_tohalf<<<(N_NODES * D / 2 + 255) / 256, 256>>>(x);
    k_wconv <<<(L * D * D + 255) / 256, 256>>>(Wl, Wr);

    __half* bufs[2];
    cudaGetSymbolAddress((void**)&bufs[0], g_hb0);
    cudaGetSymbolAddress((void**)&bufs[1], g_hb1);
    __half *hx, *hwl, *hwr;
    cudaGetSymbolAddress((void**)&hx,  g_hx);
    cudaGetSymbolAddress((void**)&hwl, g_hwl);
    cudaGetSymbolAddress((void**)&hwr, g_hwr);

    const int gemmBlocks   = (N_NODES + 127) / 128;   // 782
    const int gatherBlocks = (N_NODES + 7) / 8;       // 12500

    const __half* cur = hx;
    for (int layer = 0; layer < L; layer++) {
        __half* nxt = bufs[layer & 1];
        k_gather<<<gatherBlocks, 256>>>(cur);
        const __half* wlp = hwl + (long long)layer * D * D;
        const __half* wrp = hwr + (long long)layer * D * D;
        const float*  b   = bl + (long long)layer * D;
        if (layer < L - 1)
            k_gemm<1,0><<<gemmBlocks, 256, GEMM_SMEM>>>(cur, wlp, b, wrp, nxt);
        else
            k_gemm<0,1><<<gemmBlocks, 256, GEMM_SMEM>>>(cur, wlp, b, wrp, nxt);
        cur = nxt;
    }

    k_writeout<<<1, D>>>(out);
}

// round 10
// speedup vs baseline: 2.5237x; 1.0343x over previous
#include <cuda_runtime.h>
#include <cuda_fp16.h>
#include <cstdint>

#define N_NODES 100000
#define N_EDGES 1600000
#define D 128
#define L 3
#define SCAN_BLKS ((N_NODES + 1023) / 1024)   // 98

// ---------------- scratch (device globals; no allocation allowed) ----------
__device__ __align__(16) __half g_hx  [N_NODES * D];  // fp16 input features
__device__ __align__(16) __half g_hagg[N_NODES * D];  // fp16 mean-aggregated
__device__ __align__(16) __half g_hb0 [N_NODES * D];  // fp16 ping-pong buffers
__device__ __align__(16) __half g_hb1 [N_NODES * D];
__device__ __align__(16) __half g_hwl [L * D * D];    // fp16 weights (lin_l)
__device__ __align__(16) __half g_hwr [L * D * D];    // fp16 weights (lin_r)
__device__ int      g_cnt [N_NODES];
__device__ int      g_off [N_NODES + 1];
__device__ int      g_cur [N_NODES];
__device__ int      g_adj [N_EDGES];
__device__ int      g_bsum[128];
__device__ unsigned g_minbuf[D];

// monotone mapping: order-preserving float -> uint
__device__ __forceinline__ unsigned f2mono(float f) {
    unsigned u = __float_as_uint(f);
    return (u & 0x80000000u) ? ~u : (u | 0x80000000u);
}
__device__ __forceinline__ float mono2f(unsigned m) {
    return (m & 0x80000000u) ? __uint_as_float(m ^ 0x80000000u)
                             : __uint_as_float(~m);
}
__device__ __forceinline__ uint32_t packh2(float a, float b) {
    __half2 h = __floats2half2_rn(a, b);
    return *(uint32_t*)&h;
}

// ---------------- degree histogram (4 edges/thread) -------------------------
__global__ void k_count(const int* __restrict__ ei) {
    int q = blockIdx.x * blockDim.x + threadIdx.x;     // quad index
    if (q >= N_EDGES / 4) return;
    int4 d4 = ((const int4*)(ei + N_EDGES))[q];
    atomicAdd(&g_cnt[d4.x], 1);
    atomicAdd(&g_cnt[d4.y], 1);
    atomicAdd(&g_cnt[d4.z], 1);
    atomicAdd(&g_cnt[d4.w], 1);
}

// ---------------- hierarchical scan -----------------------------------------
__global__ void __launch_bounds__(1024) k_scanA(void) {
    __shared__ int s[1024];
    int t = threadIdx.x;
    int i = blockIdx.x * 1024 + t;
    int v = (i < N_NODES) ? g_cnt[i] : 0;
    s[t] = v;
    __syncthreads();
    for (int o = 1; o < 1024; o <<= 1) {
        int u = (t >= o) ? s[t - o] : 0;
        __syncthreads();
        s[t] += u;
        __syncthreads();
    }
    if (i < N_NODES) g_off[i] = s[t] - v;
    if (t == 1023)   g_bsum[blockIdx.x] = s[t];
}

__global__ void k_scanB(void) {
    __shared__ int s[128];
    int t = threadIdx.x;
    int v = (t < SCAN_BLKS) ? g_bsum[t] : 0;
    s[t] = v;
    __syncthreads();
    for (int o = 1; o < 128; o <<= 1) {
        int u = (t >= o) ? s[t - o] : 0;
        __syncthreads();
        s[t] += u;
        __syncthreads();
    }
    if (t < SCAN_BLKS) g_bsum[t] = s[t] - v;
    if (t == 127)      g_off[N_NODES] = s[127];
}

__global__ void k_scanC(void) {
    int i = blockIdx.x * blockDim.x + threadIdx.x;
    if (i >= N_NODES) return;
    int o = g_off[i] + g_bsum[i >> 10];
    g_off[i] = o;
    g_cur[i] = o;
}

// ---------------- CSR fill (4 edges/thread) ---------------------------------
__global__ void k_fill(const int* __restrict__ ei) {
    int q = blockIdx.x * blockDim.x + threadIdx.x;
    if (q >= N_EDGES / 4) return;
    int4 s4 = ((const int4*)ei)[q];
    int4 d4 = ((const int4*)(ei + N_EDGES))[q];
    g_adj[atomicAdd(&g_cur[d4.x], 1)] = s4.x;
    g_adj[atomicAdd(&g_cur[d4.y], 1)] = s4.y;
    g_adj[atomicAdd(&g_cur[d4.z], 1)] = s4.z;
    g_adj[atomicAdd(&g_cur[d4.w], 1)] = s4.w;
}

// ---------------- f32 -> fp16 conversions ------------------------------------
__global__ void k_tohalf(const float* __restrict__ x) {
    int i = blockIdx.x * blockDim.x + threadIdx.x;
    if (i >= N_NODES * D / 2) return;
    float2 v = ((const float2*)x)[i];
    ((__half2*)g_hx)[i] = __floats2half2_rn(v.x, v.y);
}

__global__ void k_wconv(const float* __restrict__ Wl,
                        const float* __restrict__ Wr) {
    int i = blockIdx.x * blockDim.x + threadIdx.x;
    const int HALF2S = L * D * D / 2;        // 24576 per matrix
    if (i < HALF2S) {
        float2 v = ((const float2*)Wl)[i];
        ((__half2*)g_hwl)[i] = __floats2half2_rn(v.x, v.y);
    } else if (i < 2 * HALF2S) {
        float2 v = ((const float2*)Wr)[i - HALF2S];
        ((__half2*)g_hwr)[i - HALF2S] = __floats2half2_rn(v.x, v.y);
    }
}

// ---------------- per-layer mean gather: 16 lanes per node ------------------
// Each half-warp owns one node; lane covers 8 feature columns via LDG.128.
__global__ void __launch_bounds__(256) k_gather(const __half* __restrict__ xcur) {
    int gid  = blockIdx.x * blockDim.x + threadIdx.x;
    int node = gid >> 4;
    int lane = threadIdx.x & 15;
    if (node >= N_NODES) return;

    int off0 = g_off[node];
    int off1 = g_off[node + 1];

    float4 accA = make_float4(0.f, 0.f, 0.f, 0.f);
    float4 accB = make_float4(0.f, 0.f, 0.f, 0.f);
    int i = off0;
    for (; i + 4 <= off1; i += 4) {
        int nb0 = g_adj[i + 0];
        int nb1 = g_adj[i + 1];
        int nb2 = g_adj[i + 2];
        int nb3 = g_adj[i + 3];
        uint4 u0 = ((const uint4*)(xcur + (long long)nb0 * D))[lane];
        uint4 u1 = ((const uint4*)(xcur + (long long)nb1 * D))[lane];
        uint4 u2 = ((const uint4*)(xcur + (long long)nb2 * D))[lane];
        uint4 u3 = ((const uint4*)(xcur + (long long)nb3 * D))[lane];
#pragma unroll
        for (int e = 0; e < 4; e++) {
            uint4 u = (e == 0) ? u0 : (e == 1) ? u1 : (e == 2) ? u2 : u3;
            float2 f0 = __half22float2(*(__half2*)&u.x);
            float2 f1 = __half22float2(*(__half2*)&u.y);
            float2 f2 = __half22float2(*(__half2*)&u.z);
            float2 f3 = __half22float2(*(__half2*)&u.w);
            accA.x += f0.x; accA.y += f0.y; accA.z += f1.x; accA.w += f1.y;
            accB.x += f2.x; accB.y += f2.y; accB.z += f3.x; accB.w += f3.y;
        }
    }
    for (; i < off1; i++) {
        int nb = g_adj[i];
        uint4 u = ((const uint4*)(xcur + (long long)nb * D))[lane];
        float2 f0 = __half22float2(*(__half2*)&u.x);
        float2 f1 = __half22float2(*(__half2*)&u.y);
        float2 f2 = __half22float2(*(__half2*)&u.z);
        float2 f3 = __half22float2(*(__half2*)&u.w);
        accA.x += f0.x; accA.y += f0.y; accA.z += f1.x; accA.w += f1.y;
        accB.x += f2.x; accB.y += f2.y; accB.z += f3.x; accB.w += f3.y;
    }
    float s = 1.0f / fmaxf((float)(off1 - off0), 1.0f);
    uint4 o;
    o.x = packh2(accA.x * s, accA.y * s);
    o.y = packh2(accA.z * s, accA.w * s);
    o.z = packh2(accB.x * s, accB.y * s);
    o.w = packh2(accB.z * s, accB.w * s);
    ((uint4*)(g_hagg + (long long)node * D))[lane] = o;
}

// ---------------- fp16 tensor-core fused SAGE GEMM (pipelined) ---------------
#define AS2 24
#define TILE_W (128 * AS2)   // words per matrix tile

__device__ __forceinline__ void mma_f16(float* d, const uint32_t* a,
                                        uint32_t b0, uint32_t b1) {
    asm volatile(
        "mma.sync.aligned.m16n8k16.row.col.f32.f16.f16.f32 "
        "{%0,%1,%2,%3}, {%4,%5,%6,%7}, {%8,%9}, {%0,%1,%2,%3};"
        : "+f"(d[0]), "+f"(d[1]), "+f"(d[2]), "+f"(d[3])
        : "r"(a[0]), "r"(a[1]), "r"(a[2]), "r"(a[3]), "r"(b0), "r"(b1));
}

struct R16 { uint4 a, b; };     // 16 halves = one k16 group

__device__ __forceinline__ R16 load16(const __half* __restrict__ src) {
    R16 r;
    r.a = ((const uint4*)src)[0];
    r.b = ((const uint4*)src)[1];
    return r;
}
// permuted store: [p0,p4,p1,p5][p2,p6,p3,p7]
__device__ __forceinline__ void store16(uint32_t* __restrict__ dst, R16 r) {
    ((uint4*)dst)[0] = make_uint4(r.a.x, r.b.x, r.a.y, r.b.y);
    ((uint4*)dst)[1] = make_uint4(r.a.z, r.b.z, r.a.w, r.b.w);
}

template<int RELU, int MINF>
__global__ void __launch_bounds__(256)
k_gemm(const __half* __restrict__ xcur,
       const __half* __restrict__ wl,
       const float*  __restrict__ bl,
       const __half* __restrict__ wr,
       __half* __restrict__ xnext) {
    extern __shared__ uint32_t smem[];
    uint32_t* AsBuf[2] = { smem,              smem + 2 * TILE_W };
    uint32_t* BsBuf[2] = { smem + TILE_W,     smem + 3 * TILE_W };
    unsigned* sMin = (unsigned*)(smem + 4 * TILE_W);

    int tid    = threadIdx.x;
    int wid    = tid >> 5;
    int lane   = tid & 31;
    int g      = lane >> 2;
    int c      = lane & 3;
    int warp_m = wid & 3;
    int warp_n = wid >> 2;
    int blockRow = blockIdx.x * 128;

    if (MINF && tid < 128) sMin[tid] = 0xFFFFFFFFu;

    int srow  = tid >> 1;        // staged row / weight col
    int shalf = tid & 1;         // which k16 group of the 32-k chunk
    int arow  = blockRow + srow;
    if (arow >= N_NODES) arow = N_NODES - 1;

    float acc[2][8][4];
#pragma unroll
    for (int mt = 0; mt < 2; mt++)
#pragma unroll
        for (int nt = 0; nt < 8; nt++)
#pragma unroll
            for (int r = 0; r < 4; r++) acc[mt][nt][r] = 0.f;

    const __half* aBase0 = g_hagg + (long long)arow * D + shalf * 16;
    const __half* aBase1 = xcur   + (long long)arow * D + shalf * 16;
    const __half* bBase0 = wl + (long long)srow * D + shalf * 16;
    const __half* bBase1 = wr + (long long)srow * D + shalf * 16;

    // prefetch chunk 0
    R16 ra = load16(aBase0);
    R16 rb = load16(bBase0);
    store16(&AsBuf[0][srow * AS2 + shalf * 8], ra);
    store16(&BsBuf[0][srow * AS2 + shalf * 8], rb);
    __syncthreads();

    for (int kc = 0; kc < 8; kc++) {
        int cb = kc & 1;
        if (kc < 7) {
            int nk = kc + 1;
            int kb = (nk & 3) * 32;
            ra = load16((nk < 4 ? aBase0 : aBase1) + kb);
            rb = load16((nk < 4 ? bBase0 : bBase1) + kb);
        }

        uint32_t* As = AsBuf[cb];
        uint32_t* Bs = BsBuf[cb];
#pragma unroll
        for (int ks = 0; ks < 2; ks++) {
            uint32_t a[2][4];
#pragma unroll
            for (int mt = 0; mt < 2; mt++) {
                int row = warp_m * 32 + mt * 16 + g;
                uint2 lo = *(uint2*)&As[row * AS2 + ks * 8 + 2 * c];
                uint2 hi = *(uint2*)&As[(row + 8) * AS2 + ks * 8 + 2 * c];
                a[mt][0] = lo.x; a[mt][1] = hi.x;
                a[mt][2] = lo.y; a[mt][3] = hi.y;
            }
#pragma unroll
            for (int nt = 0; nt < 8; nt++) {
                int col = warp_n * 64 + nt * 8 + g;
                uint2 b = *(uint2*)&Bs[col * AS2 + ks * 8 + 2 * c];
                mma_f16(acc[0][nt], a[0], b.x, b.y);
                mma_f16(acc[1][nt], a[1], b.x, b.y);
            }
        }

        if (kc < 7) {
            int nb = cb ^ 1;
            store16(&AsBuf[nb][srow * AS2 + shalf * 8], ra);
            store16(&BsBuf[nb][srow * AS2 + shalf * 8], rb);
            __syncthreads();
        }
    }

    // ---- epilogue ----
#pragma unroll
    for (int nt = 0; nt < 8; nt++) {
        int col = warp_n * 64 + nt * 8 + 2 * c;
        float b0 = bl[col];
        float b1 = bl[col + 1];
        if (MINF) {
            float m0 = 3.4e38f, m1 = 3.4e38f;
#pragma unroll
            for (int mt = 0; mt < 2; mt++) {
                int row0 = blockRow + warp_m * 32 + mt * 16 + g;
                if (row0 < N_NODES) {
                    m0 = fminf(m0, acc[mt][nt][0] + b0);
                    m1 = fminf(m1, acc[mt][nt][1] + b1);
                }
                if (row0 + 8 < N_NODES) {
                    m0 = fminf(m0, acc[mt][nt][2] + b0);
                    m1 = fminf(m1, acc[mt][nt][3] + b1);
                }
            }
#pragma unroll
            for (int s = 16; s >= 4; s >>= 1) {
                m0 = fminf(m0, __shfl_xor_sync(0xFFFFFFFFu, m0, s));
                m1 = fminf(m1, __shfl_xor_sync(0xFFFFFFFFu, m1, s));
            }
            if (g == 0) {
                atomicMin(&sMin[col],     f2mono(m0));
                atomicMin(&sMin[col + 1], f2mono(m1));
            }
        } else {
#pragma unroll
            for (int mt = 0; mt < 2; mt++) {
                int row0 = blockRow + warp_m * 32 + mt * 16 + g;
                float v0 = acc[mt][nt][0] + b0;
                float v1 = acc[mt][nt][1] + b1;
                float v2 = acc[mt][nt][2] + b0;
                float v3 = acc[mt][nt][3] + b1;
                if (RELU) {
                    v0 = fmaxf(v0, 0.f); v1 = fmaxf(v1, 0.f);
                    v2 = fmaxf(v2, 0.f); v3 = fmaxf(v3, 0.f);
                }
                if (row0 < N_NODES)
                    ((uint32_t*)(xnext + (long long)row0 * D))[col >> 1] = packh2(v0, v1);
                if (row0 + 8 < N_NODES)
                    ((uint32_t*)(xnext + (long long)(row0 + 8) * D))[col >> 1] = packh2(v2, v3);
            }
        }
    }

    if (MINF) {
        __syncthreads();
        if (tid < 128) atomicMin(&g_minbuf[tid], sMin[tid]);
    }
}

#define GEMM_SMEM ((4 * TILE_W + 128) * 4)   // 49664 bytes

// ---------------- final writeout --------------------------------------------
__global__ void k_writeout(float* __restrict__ out) {
    int j = threadIdx.x;
    out[j] = mono2f(g_minbuf[j]);
}

// ---------------- launch ----------------------------------------------------
extern "C" void kernel_launch(void* const* d_in, const int* in_sizes, int n_in,
                              void* d_out, int out_size) {
    const float* x  = (const float*)d_in[0];
    const int*   ei = (const int*)d_in[1];       // int32 edge index
    const float* Wl = (const float*)d_in[2];     // [L,D,D]
    const float* bl = (const float*)d_in[3];     // [L,D]
    const float* Wr = (const float*)d_in[4];     // [L,D,D]
    float*       out = (float*)d_out;

    cudaFuncSetAttribute(k_gemm<1,0>, cudaFuncAttributeMaxDynamicSharedMemorySize, GEMM_SMEM);
    cudaFuncSetAttribute(k_gemm<0,1>, cudaFuncAttributeMaxDynamicSharedMemorySize, GEMM_SMEM);

    void *p_cnt, *p_min;
    cudaGetSymbolAddress(&p_cnt, g_cnt);
    cudaGetSymbolAddress(&p_min, g_minbuf);
    cudaMemsetAsync(p_cnt, 0, N_NODES * sizeof(int));
    cudaMemsetAsync(p_min, 0xFF, D * sizeof(unsigned));

    // ---- CSR build + fp16 conversions
    k_count <<<(N_EDGES / 4 + 255) / 256, 256>>>(ei);
    k_scanA <<<SCAN_BLKS, 1024>>>();
    k_scanB <<<1, 128>>>();
    k_scanC <<<(N_NODES + 255) / 256, 256>>>();
    k_fill  <<<(N_EDGES / 4 + 255) / 256, 256>>>(ei);
    k_tohalf<<<(N_NODES * D / 2 + 255) / 256, 256>>>(x);
    k_wconv <<<(L * D * D + 255) / 256, 256>>>(Wl, Wr);

    __half* bufs[2];
    cudaGetSymbolAddress((void**)&bufs[0], g_hb0);
    cudaGetSymbolAddress((void**)&bufs[1], g_hb1);
    __half *hx, *hwl, *hwr;
    cudaGetSymbolAddress((void**)&hx,  g_hx);
    cudaGetSymbolAddress((void**)&hwl, g_hwl);
    cudaGetSymbolAddress((void**)&hwr, g_hwr);

    const int gemmBlocks   = (N_NODES + 127) / 128;   // 782
    const int gatherBlocks = (N_NODES * 16 + 255) / 256;  // 6250

    const __half* cur = hx;
    for (int layer = 0; layer < L; layer++) {
        __half* nxt = bufs[layer & 1];
        k_gather<<<gatherBlocks, 256>>>(cur);
        const __half* wlp = hwl + (long long)layer * D * D;
        const __half* wrp = hwr + (long long)layer * D * D;
        const float*  b   = bl + (long long)layer * D;
        if (layer < L - 1)
            k_gemm<1,0><<<gemmBlocks, 256, GEMM_SMEM>>>(cur, wlp, b, wrp, nxt);
        else
            k_gemm<0,1><<<gemmBlocks, 256, GEMM_SMEM>>>(cur, wlp, b, wrp, nxt);
        cur = nxt;
    }

    k_writeout<<<1, D>>>(out);
}

// round 12
// speedup vs baseline: 2.8167x; 1.1161x over previous
#include <cuda_runtime.h>
#include <cuda_fp16.h>
#include <cstdint>

#define N_NODES 100000
#define N_EDGES 1600000
#define D 128
#define L 3
#define SCAN_BLKS ((N_NODES + 1023) / 1024)   // 98

// NOTE: all fp16 feature/weight rows store each 16-half group PERMUTED as
// [p0,p4,p1,p5,p2,p6,p3,p7] (p = half2 pair) so GEMM staging is a verbatim
// copy. Gather is element-wise and layout-agnostic.

// ---------------- scratch (device globals; no allocation allowed) ----------
__device__ __align__(16) __half g_hx  [N_NODES * D];
__device__ __align__(16) __half g_hagg[N_NODES * D];
__device__ __align__(16) __half g_hb0 [N_NODES * D];
__device__ __align__(16) __half g_hb1 [N_NODES * D];
__device__ __align__(16) __half g_hwl [L * D * D];
__device__ __align__(16) __half g_hwr [L * D * D];
__device__ int      g_cnt [N_NODES];
__device__ int      g_off [N_NODES + 1];
__device__ int      g_cur [N_NODES];
__device__ int      g_adj [N_EDGES];
__device__ int      g_bsum[128];
__device__ unsigned g_minbuf[D];

__device__ __forceinline__ unsigned f2mono(float f) {
    unsigned u = __float_as_uint(f);
    return (u & 0x80000000u) ? ~u : (u | 0x80000000u);
}
__device__ __forceinline__ float mono2f(unsigned m) {
    return (m & 0x80000000u) ? __uint_as_float(m ^ 0x80000000u)
                             : __uint_as_float(~m);
}
__device__ __forceinline__ uint32_t packh2(float a, float b) {
    __half2 h = __floats2half2_rn(a, b);
    return *(uint32_t*)&h;
}

// ---------------- degree histogram (4 edges/thread) -------------------------
__global__ void k_count(const int* __restrict__ ei) {
    int q = blockIdx.x * blockDim.x + threadIdx.x;
    if (q >= N_EDGES / 4) return;
    int4 d4 = ((const int4*)(ei + N_EDGES))[q];
    atomicAdd(&g_cnt[d4.x], 1);
    atomicAdd(&g_cnt[d4.y], 1);
    atomicAdd(&g_cnt[d4.z], 1);
    atomicAdd(&g_cnt[d4.w], 1);
}

// ---------------- hierarchical scan -----------------------------------------
__global__ void __launch_bounds__(1024) k_scanA(void) {
    __shared__ int s[1024];
    int t = threadIdx.x;
    int i = blockIdx.x * 1024 + t;
    int v = (i < N_NODES) ? g_cnt[i] : 0;
    s[t] = v;
    __syncthreads();
    for (int o = 1; o < 1024; o <<= 1) {
        int u = (t >= o) ? s[t - o] : 0;
        __syncthreads();
        s[t] += u;
        __syncthreads();
    }
    if (i < N_NODES) g_off[i] = s[t] - v;
    if (t == 1023)   g_bsum[blockIdx.x] = s[t];
}

__global__ void k_scanB(void) {
    __shared__ int s[128];
    int t = threadIdx.x;
    int v = (t < SCAN_BLKS) ? g_bsum[t] : 0;
    s[t] = v;
    __syncthreads();
    for (int o = 1; o < 128; o <<= 1) {
        int u = (t >= o) ? s[t - o] : 0;
        __syncthreads();
        s[t] += u;
        __syncthreads();
    }
    if (t < SCAN_BLKS) g_bsum[t] = s[t] - v;
    if (t == 127)      g_off[N_NODES] = s[127];
}

__global__ void k_scanC(void) {
    int i = blockIdx.x * blockDim.x + threadIdx.x;
    if (i >= N_NODES) return;
    int o = g_off[i] + g_bsum[i >> 10];
    g_off[i] = o;
    g_cur[i] = o;
}

// ---------------- CSR fill (4 edges/thread) ---------------------------------
__global__ void k_fill(const int* __restrict__ ei) {
    int q = blockIdx.x * blockDim.x + threadIdx.x;
    if (q >= N_EDGES / 4) return;
    int4 s4 = ((const int4*)ei)[q];
    int4 d4 = ((const int4*)(ei + N_EDGES))[q];
    g_adj[atomicAdd(&g_cur[d4.x], 1)] = s4.x;
    g_adj[atomicAdd(&g_cur[d4.y], 1)] = s4.y;
    g_adj[atomicAdd(&g_cur[d4.z], 1)] = s4.z;
    g_adj[atomicAdd(&g_cur[d4.w], 1)] = s4.w;
}

// ---------------- f32 -> permuted fp16 conversion (x + weights) -------------
// One thread per 16-float group: emit [p0,p4,p1,p5][p2,p6,p3,p7].
__device__ __forceinline__ void conv16(const float* __restrict__ src,
                                       __half* __restrict__ dst) {
    float4 a = ((const float4*)src)[0];
    float4 b = ((const float4*)src)[1];
    float4 c = ((const float4*)src)[2];
    float4 d = ((const float4*)src)[3];
    uint32_t p0 = packh2(a.x, a.y), p1 = packh2(a.z, a.w);
    uint32_t p2 = packh2(b.x, b.y), p3 = packh2(b.z, b.w);
    uint32_t p4 = packh2(c.x, c.y), p5 = packh2(c.z, c.w);
    uint32_t p6 = packh2(d.x, d.y), p7 = packh2(d.z, d.w);
    ((uint4*)dst)[0] = make_uint4(p0, p4, p1, p5);
    ((uint4*)dst)[1] = make_uint4(p2, p6, p3, p7);
}

__global__ void k_convert(const float* __restrict__ x,
                          const float* __restrict__ Wl,
                          const float* __restrict__ Wr) {
    int g = blockIdx.x * blockDim.x + threadIdx.x;
    const int XG = N_NODES * D / 16;   // 800000
    const int WG = L * D * D / 16;     // 3072
    if (g < XG) {
        conv16(x + g * 16, g_hx + g * 16);
    } else if (g < XG + WG) {
        int h = g - XG;
        conv16(Wl + h * 16, g_hwl + h * 16);
    } else if (g < XG + 2 * WG) {
        int h = g - XG - WG;
        conv16(Wr + h * 16, g_hwr + h * 16);
    }
}

// ---------------- per-layer mean gather: 16 lanes per node ------------------
__global__ void __launch_bounds__(256) k_gather(const __half* __restrict__ xcur) {
    int gid  = blockIdx.x * blockDim.x + threadIdx.x;
    int node = gid >> 4;
    int lane = threadIdx.x & 15;
    if (node >= N_NODES) return;

    int off0 = g_off[node];
    int off1 = g_off[node + 1];

    float4 accA = make_float4(0.f, 0.f, 0.f, 0.f);
    float4 accB = make_float4(0.f, 0.f, 0.f, 0.f);
    int i = off0;
    for (; i + 4 <= off1; i += 4) {
        int nb0 = g_adj[i + 0];
        int nb1 = g_adj[i + 1];
        int nb2 = g_adj[i + 2];
        int nb3 = g_adj[i + 3];
        uint4 u0 = ((const uint4*)(xcur + (long long)nb0 * D))[lane];
        uint4 u1 = ((const uint4*)(xcur + (long long)nb1 * D))[lane];
        uint4 u2 = ((const uint4*)(xcur + (long long)nb2 * D))[lane];
        uint4 u3 = ((const uint4*)(xcur + (long long)nb3 * D))[lane];
#pragma unroll
        for (int e = 0; e < 4; e++) {
            uint4 u = (e == 0) ? u0 : (e == 1) ? u1 : (e == 2) ? u2 : u3;
            float2 f0 = __half22float2(*(__half2*)&u.x);
            float2 f1 = __half22float2(*(__half2*)&u.y);
            float2 f2 = __half22float2(*(__half2*)&u.z);
            float2 f3 = __half22float2(*(__half2*)&u.w);
            accA.x += f0.x; accA.y += f0.y; accA.z += f1.x; accA.w += f1.y;
            accB.x += f2.x; accB.y += f2.y; accB.z += f3.x; accB.w += f3.y;
        }
    }
    for (; i < off1; i++) {
        int nb = g_adj[i];
        uint4 u = ((const uint4*)(xcur + (long long)nb * D))[lane];
        float2 f0 = __half22float2(*(__half2*)&u.x);
        float2 f1 = __half22float2(*(__half2*)&u.y);
        float2 f2 = __half22float2(*(__half2*)&u.z);
        float2 f3 = __half22float2(*(__half2*)&u.w);
        accA.x += f0.x; accA.y += f0.y; accA.z += f1.x; accA.w += f1.y;
        accB.x += f2.x; accB.y += f2.y; accB.z += f3.x; accB.w += f3.y;
    }
    float s = 1.0f / fmaxf((float)(off1 - off0), 1.0f);
    uint4 o;
    o.x = packh2(accA.x * s, accA.y * s);
    o.y = packh2(accA.z * s, accA.w * s);
    o.z = packh2(accB.x * s, accB.y * s);
    o.w = packh2(accB.z * s, accB.w * s);
    ((uint4*)(g_hagg + (long long)node * D))[lane] = o;
}

// ---------------- fp16 tensor-core fused SAGE GEMM (cp.async pipelined) ------
#define AS2 24
#define TILE_W (128 * AS2)   // words per matrix tile

__device__ __forceinline__ void mma_f16v(float* d, const uint32_t* a,
                                         uint32_t b0, uint32_t b1) {
    asm volatile(
        "mma.sync.aligned.m16n8k16.row.col.f32.f16.f16.f32 "
        "{%0,%1,%2,%3}, {%4,%5,%6,%7}, {%8,%9}, {%0,%1,%2,%3};"
        : "+f"(d[0]), "+f"(d[1]), "+f"(d[2]), "+f"(d[3])
        : "r"(a[0]), "r"(a[1]), "r"(a[2]), "r"(a[3]), "r"(b0), "r"(b1));
}

__device__ __forceinline__ void cp16(uint32_t smem_dst, const void* gmem_src) {
    asm volatile("cp.async.ca.shared.global [%0], [%1], 16;"
                 :: "r"(smem_dst), "l"(gmem_src));
}
__device__ __forceinline__ void cp_commit(void) {
    asm volatile("cp.async.commit_group;");
}
__device__ __forceinline__ void cp_wait0(void) {
    asm volatile("cp.async.wait_group 0;");
}

template<int RELU, int MINF>
__global__ void __launch_bounds__(256)
k_gemm(const __half* __restrict__ xcur,
       const __half* __restrict__ wl,
       const float*  __restrict__ bl,
       const __half* __restrict__ wr,
       __half* __restrict__ xnext) {
    extern __shared__ uint32_t smem[];
    uint32_t* AsBuf[2] = { smem,          smem + 2 * TILE_W };
    uint32_t* BsBuf[2] = { smem + TILE_W, smem + 3 * TILE_W };
    unsigned* sMin = (unsigned*)(smem + 4 * TILE_W);

    int tid    = threadIdx.x;
    int wid    = tid >> 5;
    int lane   = tid & 31;
    int g      = lane >> 2;
    int c      = lane & 3;
    int warp_m = wid & 3;
    int warp_n = wid >> 2;
    int blockRow = blockIdx.x * 128;

    if (MINF && tid < 128) sMin[tid] = 0xFFFFFFFFu;

    int srow  = tid >> 1;
    int shalf = tid & 1;
    int arow  = blockRow + srow;
    if (arow >= N_NODES) arow = N_NODES - 1;

    float acc[2][8][4];
#pragma unroll
    for (int mt = 0; mt < 2; mt++)
#pragma unroll
        for (int nt = 0; nt < 8; nt++)
#pragma unroll
            for (int r = 0; r < 4; r++) acc[mt][nt][r] = 0.f;

    const __half* aBase0 = g_hagg + (long long)arow * D + shalf * 16;
    const __half* aBase1 = xcur   + (long long)arow * D + shalf * 16;
    const __half* bBase0 = wl + (long long)srow * D + shalf * 16;
    const __half* bBase1 = wr + (long long)srow * D + shalf * 16;

    uint32_t sA[2], sB[2];
    sA[0] = (uint32_t)__cvta_generic_to_shared(&AsBuf[0][srow * AS2 + shalf * 8]);
    sA[1] = (uint32_t)__cvta_generic_to_shared(&AsBuf[1][srow * AS2 + shalf * 8]);
    sB[0] = (uint32_t)__cvta_generic_to_shared(&BsBuf[0][srow * AS2 + shalf * 8]);
    sB[1] = (uint32_t)__cvta_generic_to_shared(&BsBuf[1][srow * AS2 + shalf * 8]);

    // prefetch chunk 0
    cp16(sA[0],      aBase0);
    cp16(sA[0] + 16, (const char*)aBase0 + 16);
    cp16(sB[0],      bBase0);
    cp16(sB[0] + 16, (const char*)bBase0 + 16);
    cp_commit();
    cp_wait0();
    __syncthreads();

    for (int kc = 0; kc < 8; kc++) {
        int cb = kc & 1;
        if (kc < 7) {
            int nk = kc + 1;
            int kb = (nk & 3) * 32;   // halves
            const __half* asrc = (nk < 4 ? aBase0 : aBase1) + kb;
            const __half* bsrc = (nk < 4 ? bBase0 : bBase1) + kb;
            int nb = cb ^ 1;
            cp16(sA[nb],      asrc);
            cp16(sA[nb] + 16, (const char*)asrc + 16);
            cp16(sB[nb],      bsrc);
            cp16(sB[nb] + 16, (const char*)bsrc + 16);
            cp_commit();
        }

        uint32_t* As = AsBuf[cb];
        uint32_t* Bs = BsBuf[cb];
#pragma unroll
        for (int ks = 0; ks < 2; ks++) {
            uint32_t a[2][4];
#pragma unroll
            for (int mt = 0; mt < 2; mt++) {
                int row = warp_m * 32 + mt * 16 + g;
                uint2 lo = *(uint2*)&As[row * AS2 + ks * 8 + 2 * c];
                uint2 hi = *(uint2*)&As[(row + 8) * AS2 + ks * 8 + 2 * c];
                a[mt][0] = lo.x; a[mt][1] = hi.x;
                a[mt][2] = lo.y; a[mt][3] = hi.y;
            }
#pragma unroll
            for (int nt = 0; nt < 8; nt++) {
                int col = warp_n * 64 + nt * 8 + g;
                uint2 b = *(uint2*)&Bs[col * AS2 + ks * 8 + 2 * c];
                mma_f16v(acc[0][nt], a[0], b.x, b.y);
                mma_f16v(acc[1][nt], a[1], b.x, b.y);
            }
        }

        if (kc < 7) {
            cp_wait0();
            __syncthreads();
        }
    }

    // ---- epilogue ----
#pragma unroll
    for (int nt = 0; nt < 8; nt++) {
        int col = warp_n * 64 + nt * 8 + 2 * c;    // logical column
        float b0 = bl[col];
        float b1 = bl[col + 1];
        if (MINF) {
            float m0 = 3.4e38f, m1 = 3.4e38f;
#pragma unroll
            for (int mt = 0; mt < 2; mt++) {
                int row0 = blockRow + warp_m * 32 + mt * 16 + g;
                if (row0 < N_NODES) {
                    m0 = fminf(m0, acc[mt][nt][0] + b0);
                    m1 = fminf(m1, acc[mt][nt][1] + b1);
                }
                if (row0 + 8 < N_NODES) {
                    m0 = fminf(m0, acc[mt][nt][2] + b0);
                    m1 = fminf(m1, acc[mt][nt][3] + b1);
                }
            }
#pragma unroll
            for (int s = 16; s >= 4; s >>= 1) {
                m0 = fminf(m0, __shfl_xor_sync(0xFFFFFFFFu, m0, s));
                m1 = fminf(m1, __shfl_xor_sync(0xFFFFFFFFu, m1, s));
            }
            if (g == 0) {
                atomicMin(&sMin[col],     f2mono(m0));
                atomicMin(&sMin[col + 1], f2mono(m1));
            }
        } else {
            // permuted store: logical pair q -> slot (q&~7) | ((q&3)*2 + (q>>2)&1)
            int q    = col >> 1;
            int slot = (q & ~7) | (((q & 3) << 1) | ((q >> 2) & 1));
#pragma unroll
            for (int mt = 0; mt < 2; mt++) {
                int row0 = blockRow + warp_m * 32 + mt * 16 + g;
                float v0 = acc[mt][nt][0] + b0;
                float v1 = acc[mt][nt][1] + b1;
                float v2 = acc[mt][nt][2] + b0;
                float v3 = acc[mt][nt][3] + b1;
                if (RELU) {
                    v0 = fmaxf(v0, 0.f); v1 = fmaxf(v1, 0.f);
                    v2 = fmaxf(v2, 0.f); v3 = fmaxf(v3, 0.f);
                }
                if (row0 < N_NODES)
                    ((uint32_t*)(xnext + (long long)row0 * D))[slot] = packh2(v0, v1);
                if (row0 + 8 < N_NODES)
                    ((uint32_t*)(xnext + (long long)(row0 + 8) * D))[slot] = packh2(v2, v3);
            }
        }
    }

    if (MINF) {
        __syncthreads();
        if (tid < 128) atomicMin(&g_minbuf[tid], sMin[tid]);
    }
}

#define GEMM_SMEM ((4 * TILE_W + 128) * 4)   // 49664 bytes

// ---------------- final writeout --------------------------------------------
__global__ void k_writeout(float* __restrict__ out) {
    int j = threadIdx.x;
    out[j] = mono2f(g_minbuf[j]);
}

// ---------------- launch ----------------------------------------------------
extern "C" void kernel_launch(void* const* d_in, const int* in_sizes, int n_in,
                              void* d_out, int out_size) {
    const float* x  = (const float*)d_in[0];
    const int*   ei = (const int*)d_in[1];
    const float* Wl = (const float*)d_in[2];
    const float* bl = (const float*)d_in[3];
    const float* Wr = (const float*)d_in[4];
    float*       out = (float*)d_out;

    cudaFuncSetAttribute(k_gemm<1,0>, cudaFuncAttributeMaxDynamicSharedMemorySize, GEMM_SMEM);
    cudaFuncSetAttribute(k_gemm<0,1>, cudaFuncAttributeMaxDynamicSharedMemorySize, GEMM_SMEM);

    void *p_cnt, *p_min;
    cudaGetSymbolAddress(&p_cnt, g_cnt);
    cudaGetSymbolAddress(&p_min, g_minbuf);
    cudaMemsetAsync(p_cnt, 0, N_NODES * sizeof(int));
    cudaMemsetAsync(p_min, 0xFF, D * sizeof(unsigned));

    const int CONV_G = N_NODES * D / 16 + 2 * (L * D * D / 16);  // 806144

    k_count  <<<(N_EDGES / 4 + 255) / 256, 256>>>(ei);
    k_scanA  <<<SCAN_BLKS, 1024>>>();
    k_scanB  <<<1, 128>>>();
    k_scanC  <<<(N_NODES + 255) / 256, 256>>>();
    k_fill   <<<(N_EDGES / 4 + 255) / 256, 256>>>(ei);
    k_convert<<<(CONV_G + 255) / 256, 256>>>(x, Wl, Wr);

    __half* bufs[2];
    cudaGetSymbolAddress((void**)&bufs[0], g_hb0);
    cudaGetSymbolAddress((void**)&bufs[1], g_hb1);
    __half *hx, *hwl, *hwr;
    cudaGetSymbolAddress((void**)&hx,  g_hx);
    cudaGetSymbolAddress((void**)&hwl, g_hwl);
    cudaGetSymbolAddress((void**)&hwr, g_hwr);

    const int gemmBlocks   = (N_NODES + 127) / 128;       // 782
    const int gatherBlocks = (N_NODES * 16 + 255) / 256;  // 6250

    const __half* cur = hx;
    for (int layer = 0; layer < L; layer++) {
        __half* nxt = bufs[layer & 1];
        k_gather<<<gatherBlocks, 256>>>(cur);
        const __half* wlp = hwl + (long long)layer * D * D;
        const __half* wrp = hwr + (long long)layer * D * D;
        const float*  b   = bl + (long long)layer * D;
        if (layer < L - 1)
            k_gemm<1,0><<<gemmBlocks, 256, GEMM_SMEM>>>(cur, wlp, b, wrp, nxt);
        else
            k_gemm<0,1><<<gemmBlocks, 256, GEMM_SMEM>>>(cur, wlp, b, wrp, nxt);
        cur = nxt;
    }

    k_writeout<<<1, D>>>(out);
}